// round 9
// baseline (speedup 1.0000x reference)
#include <cuda_runtime.h>
#include <cuda_bf16.h>
#include <cstdint>

// Problem constants
#define NN 100000
#define NE 1600000

// ---------------- scratch (device globals) ----------------------------------
__device__ float g_H[(size_t)NN * 128];          // GEMM out (dinv-prescaled)
__device__ __nv_bfloat16 g_Gh[(size_t)NN * 128]; // agg out hi (next GEMM A)
__device__ __nv_bfloat16 g_Gl[(size_t)NN * 128]; // agg out lo
__device__ int   g_deg[NN];
__device__ int   g_rowptr[NN + 1];
__device__ int   g_cursor[NN];
__device__ int   g_col[NE];
__device__ float g_dinv[NN];
__device__ int   g_scantmp[NN];
__device__ int   g_bsums[128];
// W1 / Wm transposed + split into bf16 hi/lo, layout [n][k]
__device__ __nv_bfloat16 g_Wth[2][128 * 128];
__device__ __nv_bfloat16 g_Wtl[2][128 * 128];

// ---------------- graph prep -----------------------------------------------
__global__ void k_zero_deg(int n) {
    int i = blockIdx.x * blockDim.x + threadIdx.x;
    if (i < n) g_deg[i] = 0;
}
__global__ void k_count(const int* __restrict__ dst, int e) {
    int i = blockIdx.x * blockDim.x + threadIdx.x;
    if (i < e) atomicAdd(&g_deg[dst[i]], 1);
}
__global__ void k_scan_block(int n) {
    int tid = threadIdx.x, lane = tid & 31, wid = tid >> 5;
    int i = blockIdx.x * 1024 + tid;
    int v = (i < n) ? g_deg[i] : 0;
    #pragma unroll
    for (int o = 1; o < 32; o <<= 1) {
        int t = __shfl_up_sync(0xffffffffu, v, o);
        if (lane >= o) v += t;
    }
    __shared__ int ws[32];
    if (lane == 31) ws[wid] = v;
    __syncthreads();
    if (wid == 0) {
        int w = ws[lane];
        #pragma unroll
        for (int o = 1; o < 32; o <<= 1) {
            int t = __shfl_up_sync(0xffffffffu, w, o);
            if (lane >= o) w += t;
        }
        ws[lane] = w;
    }
    __syncthreads();
    if (wid > 0) v += ws[wid - 1];
    if (i < n) g_scantmp[i] = v;
    if (tid == 1023) g_bsums[blockIdx.x] = v;
}
__global__ void k_scan_sums(int nb) {
    if (threadIdx.x == 0 && blockIdx.x == 0) {
        int acc = 0;
        for (int b = 0; b < nb; b++) {
            int t = g_bsums[b];
            g_bsums[b] = acc;
            acc += t;
        }
    }
}
__global__ void k_finalize(int n) {
    int i = blockIdx.x * 1024 + threadIdx.x;
    if (i >= n) return;
    int incl = g_scantmp[i] + g_bsums[blockIdx.x];
    int d = g_deg[i];
    int excl = incl - d;
    g_cursor[i] = excl;
    g_rowptr[i] = excl;
    if (i == n - 1) g_rowptr[n] = incl;
    g_dinv[i] = rsqrtf((float)(d + 1));
}
__global__ void k_scatter(const int* __restrict__ src,
                          const int* __restrict__ dst, int e) {
    int i = blockIdx.x * blockDim.x + threadIdx.x;
    if (i < e) {
        int d = dst[i];
        int p = atomicAdd(&g_cursor[d], 1);
        g_col[p] = src[i];
    }
}

// ---------------- W prep: W[k][n] f32 -> Wt[n][k] bf16 hi/lo ---------------
__global__ void k_wconv(const float* __restrict__ W, int slot) {
    int idx = blockIdx.x * blockDim.x + threadIdx.x;
    if (idx >= 128 * 128) return;
    int n = idx >> 7, k = idx & 127;
    float w = W[(size_t)k * 128 + n];
    __nv_bfloat16 h = __float2bfloat16_rn(w);
    __nv_bfloat16 l = __float2bfloat16_rn(w - __bfloat162float(h));
    g_Wth[slot][n * 128 + k] = h;
    g_Wtl[slot][n * 128 + k] = l;
}

// ---------------- mma helper -----------------------------------------------
__device__ __forceinline__ void mma_bf16(float* c, const uint32_t* a,
                                         const uint32_t* b) {
    asm volatile(
        "mma.sync.aligned.m16n8k16.row.col.f32.bf16.bf16.f32 "
        "{%0,%1,%2,%3}, {%4,%5,%6,%7}, {%8,%9}, {%0,%1,%2,%3};"
        : "+f"(c[0]), "+f"(c[1]), "+f"(c[2]), "+f"(c[3])
        : "r"(a[0]), "r"(a[1]), "r"(a[2]), "r"(a[3]), "r"(b[0]), "r"(b[1]));
}

// ---------------- split-bf16 tensor GEMM: H[M,128] = dinv*(A @ W) ----------
// A_SEL: 0 = fp32 param (convert in-kernel), 1 = bf16 g_Gh/g_Gl (direct).
#define KP 40
template <int A_SEL>
__global__ void __launch_bounds__(256)
gemm128_mma_k(const float* __restrict__ Ap, int wslot, int M) {
    float* __restrict__ C = (float*)g_H;

    __shared__ __nv_bfloat16 Ash[128][KP];
    __shared__ __nv_bfloat16 Asl[128][KP];
    __shared__ __nv_bfloat16 Wsh[128][KP];
    __shared__ __nv_bfloat16 Wsl[128][KP];

    const int tid = threadIdx.x;
    const int wid = tid >> 5;
    const int lane = tid & 31;
    const int gid = lane >> 2;
    const int tig = lane & 3;
    const int mw = wid & 3;
    const int nw = wid >> 2;
    const int rowBase = blockIdx.x * 128;

    const int ar  = tid >> 1;
    const int akl = (tid & 1) * 16;
    const int wn  = tid >> 1;
    const int wkl = (tid & 1) * 16;

    float acc[2][8][4];
    #pragma unroll
    for (int i = 0; i < 2; i++)
        #pragma unroll
        for (int j = 0; j < 8; j++)
            #pragma unroll
            for (int q = 0; q < 4; q++) acc[i][j][q] = 0.f;

    const __nv_bfloat16* __restrict__ Wth = g_Wth[wslot];
    const __nv_bfloat16* __restrict__ Wtl = g_Wtl[wslot];

    for (int kt = 0; kt < 128; kt += 32) {
        // ---- stage A chunk
        if (A_SEL == 0) {
            const int gr = rowBase + ar;
            const bool valid = (gr < M);
            #pragma unroll
            for (int j = 0; j < 4; j++) {
                float4 v = valid
                    ? *(const float4*)&Ap[(size_t)gr * 128 + kt + akl + j * 4]
                    : make_float4(0.f, 0.f, 0.f, 0.f);
                float f[4] = {v.x, v.y, v.z, v.w};
                #pragma unroll
                for (int q = 0; q < 4; q++) {
                    __nv_bfloat16 h = __float2bfloat16_rn(f[q]);
                    __nv_bfloat16 l =
                        __float2bfloat16_rn(f[q] - __bfloat162float(h));
                    Ash[ar][akl + j * 4 + q] = h;
                    Asl[ar][akl + j * 4 + q] = l;
                }
            }
        } else {
            const int gr = rowBase + ar;
            const size_t base = (size_t)gr * 128 + kt + akl;
            uint4 z = make_uint4(0, 0, 0, 0);
            uint4 h0 = z, h1 = z, l0 = z, l1 = z;
            if (gr < M) {
                h0 = *(const uint4*)&g_Gh[base];
                h1 = *(const uint4*)&g_Gh[base + 8];
                l0 = *(const uint4*)&g_Gl[base];
                l1 = *(const uint4*)&g_Gl[base + 8];
            }
            *(uint4*)&Ash[ar][akl]     = h0;
            *(uint4*)&Ash[ar][akl + 8] = h1;
            *(uint4*)&Asl[ar][akl]     = l0;
            *(uint4*)&Asl[ar][akl + 8] = l1;
        }
        // ---- stage W chunk
        {
            const size_t base = (size_t)wn * 128 + kt + wkl;
            uint4 vh0 = *(const uint4*)&Wth[base];
            uint4 vh1 = *(const uint4*)&Wth[base + 8];
            uint4 vl0 = *(const uint4*)&Wtl[base];
            uint4 vl1 = *(const uint4*)&Wtl[base + 8];
            *(uint4*)&Wsh[wn][wkl]     = vh0;
            *(uint4*)&Wsh[wn][wkl + 8] = vh1;
            *(uint4*)&Wsl[wn][wkl]     = vl0;
            *(uint4*)&Wsl[wn][wkl + 8] = vl1;
        }
        __syncthreads();

        #pragma unroll
        for (int ks = 0; ks < 32; ks += 16) {
            uint32_t Ah[2][4], Al[2][4], Bh[8][2], Bl[8][2];
            #pragma unroll
            for (int mt = 0; mt < 2; mt++) {
                const int r = mw * 32 + mt * 16 + gid;
                Ah[mt][0] = *(const uint32_t*)&Ash[r][ks + tig * 2];
                Ah[mt][1] = *(const uint32_t*)&Ash[r + 8][ks + tig * 2];
                Ah[mt][2] = *(const uint32_t*)&Ash[r][ks + 8 + tig * 2];
                Ah[mt][3] = *(const uint32_t*)&Ash[r + 8][ks + 8 + tig * 2];
                Al[mt][0] = *(const uint32_t*)&Asl[r][ks + tig * 2];
                Al[mt][1] = *(const uint32_t*)&Asl[r + 8][ks + tig * 2];
                Al[mt][2] = *(const uint32_t*)&Asl[r][ks + 8 + tig * 2];
                Al[mt][3] = *(const uint32_t*)&Asl[r + 8][ks + 8 + tig * 2];
            }
            #pragma unroll
            for (int nt = 0; nt < 8; nt++) {
                const int nn = nw * 64 + nt * 8 + gid;
                Bh[nt][0] = *(const uint32_t*)&Wsh[nn][ks + tig * 2];
                Bh[nt][1] = *(const uint32_t*)&Wsh[nn][ks + 8 + tig * 2];
                Bl[nt][0] = *(const uint32_t*)&Wsl[nn][ks + tig * 2];
                Bl[nt][1] = *(const uint32_t*)&Wsl[nn][ks + 8 + tig * 2];
            }
            #pragma unroll
            for (int mt = 0; mt < 2; mt++)
                #pragma unroll
                for (int nt = 0; nt < 8; nt++)
                    mma_bf16(acc[mt][nt], Ah[mt], Bh[nt]);
            #pragma unroll
            for (int mt = 0; mt < 2; mt++)
                #pragma unroll
                for (int nt = 0; nt < 8; nt++)
                    mma_bf16(acc[mt][nt], Ah[mt], Bl[nt]);
            #pragma unroll
            for (int mt = 0; mt < 2; mt++)
                #pragma unroll
                for (int nt = 0; nt < 8; nt++)
                    mma_bf16(acc[mt][nt], Al[mt], Bh[nt]);
        }
        __syncthreads();
    }

    // ---- epilogue: scale row by dinv[row], store fp32
    #pragma unroll
    for (int mt = 0; mt < 2; mt++) {
        const int r = rowBase + mw * 32 + mt * 16 + gid;
        const float di0 = (r < M) ? g_dinv[r] : 0.f;
        const float di1 = (r + 8 < M) ? g_dinv[r + 8] : 0.f;
        #pragma unroll
        for (int nt = 0; nt < 8; nt++) {
            const int col = nw * 64 + nt * 8 + tig * 2;
            if (r < M)
                *(float2*)&C[(size_t)r * 128 + col] =
                    make_float2(di0 * acc[mt][nt][0], di0 * acc[mt][nt][1]);
            if (r + 8 < M)
                *(float2*)&C[(size_t)(r + 8) * 128 + col] =
                    make_float2(di1 * acc[mt][nt][2], di1 * acc[mt][nt][3]);
        }
    }
}

// ---------------- small GEMM layer 3: H[M,40] = dinv*(G @ W2) ---------------
// A reconstructed from bf16 hi+lo.
__global__ void gemm40_k(const float* __restrict__ W, int M) {
    float* __restrict__ C = (float*)g_H;
    constexpr int BM = 64, BK = 32, K = 128, BN = 64, NA = 40;
    __shared__ float As[BM][BK];
    __shared__ float Ws[BK][BN];
    int tid = threadIdx.x;
    int tx = tid % 16;
    int ty = tid / 16;
    int rowBase = blockIdx.x * BM;

    float acc[4][4];
    #pragma unroll
    for (int i = 0; i < 4; i++)
        #pragma unroll
        for (int j = 0; j < 4; j++) acc[i][j] = 0.f;

    for (int kt = 0; kt < K; kt += BK) {
        #pragma unroll
        for (int t = 0; t < (BM * BK) / 256; t++) {
            int idx = tid + t * 256;
            int r = idx / BK, kk = idx % BK;
            int gr = rowBase + r;
            float v = 0.f;
            if (gr < M) {
                size_t o = (size_t)gr * K + kt + kk;
                v = __bfloat162float(g_Gh[o]) + __bfloat162float(g_Gl[o]);
            }
            As[r][kk] = v;
        }
        #pragma unroll
        for (int t = 0; t < (BK * BN) / 256; t++) {
            int idx = tid + t * 256;
            int r = idx / BN, c = idx % BN;
            Ws[r][c] = (c < NA) ? W[(kt + r) * NA + c] : 0.f;
        }
        __syncthreads();
        #pragma unroll
        for (int kk = 0; kk < BK; kk++) {
            float b0 = Ws[kk][tx * 4 + 0];
            float b1 = Ws[kk][tx * 4 + 1];
            float b2 = Ws[kk][tx * 4 + 2];
            float b3 = Ws[kk][tx * 4 + 3];
            #pragma unroll
            for (int i = 0; i < 4; i++) {
                float a = As[ty * 4 + i][kk];
                acc[i][0] += a * b0;
                acc[i][1] += a * b1;
                acc[i][2] += a * b2;
                acc[i][3] += a * b3;
            }
        }
        __syncthreads();
    }
    #pragma unroll
    for (int i = 0; i < 4; i++) {
        int gr = rowBase + ty * 4 + i;
        if (gr >= M) continue;
        float di = g_dinv[gr];
        #pragma unroll
        for (int j = 0; j < 4; j++) {
            int c = tx * 4 + j;
            if (c < NA) C[(size_t)gr * NA + c] = di * acc[i][j];
        }
    }
}

// ---------------- aggregation, F=128 ----------------------------------------
// H pre-scaled by dinv. out = dinv[i]*(sum + self) + b, relu, write bf16 hi/lo.
__global__ void agg128_k(const float* __restrict__ bias, int n) {
    int node = blockIdx.x * (blockDim.x >> 5) + (threadIdx.x >> 5);
    if (node >= n) return;
    int lane = threadIdx.x & 31;
    const float4* __restrict__ H4 = (const float4*)g_H;
    float di = g_dinv[node];
    float4 h = H4[(size_t)node * 32 + lane];
    float ax = h.x, ay = h.y, az = h.z, aw = h.w;   // self term (pre-scaled)
    int p = g_rowptr[node], pend = g_rowptr[node + 1];
    for (; p + 4 <= pend; p += 4) {
        int s0 = g_col[p], s1 = g_col[p + 1], s2 = g_col[p + 2], s3 = g_col[p + 3];
        float4 h0 = H4[(size_t)s0 * 32 + lane];
        float4 h1 = H4[(size_t)s1 * 32 + lane];
        float4 h2 = H4[(size_t)s2 * 32 + lane];
        float4 h3 = H4[(size_t)s3 * 32 + lane];
        ax += h0.x; ay += h0.y; az += h0.z; aw += h0.w;
        ax += h1.x; ay += h1.y; az += h1.z; aw += h1.w;
        ax += h2.x; ay += h2.y; az += h2.z; aw += h2.w;
        ax += h3.x; ay += h3.y; az += h3.z; aw += h3.w;
    }
    for (; p < pend; p++) {
        int s = g_col[p];
        float4 hs = H4[(size_t)s * 32 + lane];
        ax += hs.x; ay += hs.y; az += hs.z; aw += hs.w;
    }
    float4 bv = ((const float4*)bias)[lane];
    float o[4];
    o[0] = fmaxf(di * ax + bv.x, 0.f);
    o[1] = fmaxf(di * ay + bv.y, 0.f);
    o[2] = fmaxf(di * az + bv.z, 0.f);
    o[3] = fmaxf(di * aw + bv.w, 0.f);
    // split to bf16 hi/lo and store (4 cols per lane = 8B per array)
    __nv_bfloat16 hh[4], ll[4];
    #pragma unroll
    for (int q = 0; q < 4; q++) {
        hh[q] = __float2bfloat16_rn(o[q]);
        ll[q] = __float2bfloat16_rn(o[q] - __bfloat162float(hh[q]));
    }
    *(uint2*)&g_Gh[(size_t)node * 128 + lane * 4] = *(uint2*)hh;
    *(uint2*)&g_Gl[(size_t)node * 128 + lane * 4] = *(uint2*)ll;
}

// ---------------- aggregation, F=40 (H pre-scaled) --------------------------
__global__ void agg40_k(const float* __restrict__ bias, float* __restrict__ O, int n) {
    int node = blockIdx.x * (blockDim.x >> 5) + (threadIdx.x >> 5);
    if (node >= n) return;
    int lane = threadIdx.x & 31;
    const float* __restrict__ H = (const float*)g_H;
    bool hi = (lane < 8);
    float di = g_dinv[node];
    float a0 = H[(size_t)node * 40 + lane];
    float a1 = hi ? H[(size_t)node * 40 + 32 + lane] : 0.f;
    int p = g_rowptr[node], pend = g_rowptr[node + 1];
    for (; p + 2 <= pend; p += 2) {
        int s0 = g_col[p], s1 = g_col[p + 1];
        a0 += H[(size_t)s0 * 40 + lane] + H[(size_t)s1 * 40 + lane];
        if (hi) {
            a1 += H[(size_t)s0 * 40 + 32 + lane];
            a1 += H[(size_t)s1 * 40 + 32 + lane];
        }
    }
    for (; p < pend; p++) {
        int s = g_col[p];
        a0 += H[(size_t)s * 40 + lane];
        if (hi) a1 += H[(size_t)s * 40 + 32 + lane];
    }
    O[(size_t)node * 40 + lane] = di * a0 + bias[lane];
    if (hi) O[(size_t)node * 40 + 32 + lane] = di * a1 + bias[32 + lane];
}

// ---------------- launch ----------------------------------------------------
extern "C" void kernel_launch(void* const* d_in, const int* in_sizes, int n_in,
                              void* d_out, int out_size) {
    const float* x   = (const float*)d_in[0];
    const int*   ei  = (const int*)d_in[1];    // int32 (JAX x64 disabled)
    const float* W1  = (const float*)d_in[2];
    const float* b1  = (const float*)d_in[3];
    const float* Wm  = (const float*)d_in[4];
    const float* bm  = (const float*)d_in[5];
    const float* W2  = (const float*)d_in[6];
    const float* b2  = (const float*)d_in[7];
    float* out = (float*)d_out;

    const int n = NN, e = NE;
    const int* src = ei;
    const int* dst = ei + e;

    const int scanBlocks = (n + 1023) / 1024;

    // graph prep + weight conversion
    k_zero_deg<<<(n + 255) / 256, 256>>>(n);
    k_count<<<(e + 255) / 256, 256>>>(dst, e);
    k_scan_block<<<scanBlocks, 1024>>>(n);
    k_scan_sums<<<1, 32>>>(scanBlocks);
    k_finalize<<<scanBlocks, 1024>>>(n);
    k_scatter<<<(e + 255) / 256, 256>>>(src, dst, e);
    k_wconv<<<64, 256>>>(W1, 0);
    k_wconv<<<64, 256>>>(Wm, 1);

    const int tcBlocks  = (n + 127) / 128;
    const int aggBlocks = (n + 7) / 8;

    // layer 1
    gemm128_mma_k<0><<<tcBlocks, 256>>>(x, 0, n);
    agg128_k<<<aggBlocks, 256>>>(b1, n);

    // layer 2
    gemm128_mma_k<1><<<tcBlocks, 256>>>(nullptr, 1, n);
    agg128_k<<<aggBlocks, 256>>>(bm, n);

    // layer 3
    gemm40_k<<<(n + 63) / 64, 256>>>(W2, n);
    agg40_k<<<aggBlocks, 256>>>(b2, out, n);
}

// round 10
// speedup vs baseline: 1.4230x; 1.4230x over previous
#include <cuda_runtime.h>
#include <cuda_bf16.h>
#include <cstdint>

// Problem constants
#define NN 100000
#define NE 1600000

// ---------------- scratch (device globals) ----------------------------------
__device__ float g_H[(size_t)NN * 128];
__device__ float g_G[(size_t)NN * 128];
__device__ int   g_deg[NN];
__device__ int   g_rowptr[NN + 1];
__device__ int   g_cursor[NN];
__device__ int   g_col[NE];
__device__ float g_dinv[NN];
__device__ int   g_scantmp[NN];
__device__ int   g_bsums[128];
// W1 / Wm transposed + split into bf16 hi/lo, layout [n][k] (n-major)
__device__ __nv_bfloat16 g_Wth[2][128 * 128];
__device__ __nv_bfloat16 g_Wtl[2][128 * 128];

// ---------------- graph prep -----------------------------------------------
__global__ void k_zero_deg(int n) {
    int i = blockIdx.x * blockDim.x + threadIdx.x;
    if (i < n) g_deg[i] = 0;
}
__global__ void k_count(const int* __restrict__ dst, int e) {
    int i = blockIdx.x * blockDim.x + threadIdx.x;
    if (i < e) atomicAdd(&g_deg[dst[i]], 1);
}
__global__ void k_scan_block(int n) {
    int tid = threadIdx.x, lane = tid & 31, wid = tid >> 5;
    int i = blockIdx.x * 1024 + tid;
    int v = (i < n) ? g_deg[i] : 0;
    #pragma unroll
    for (int o = 1; o < 32; o <<= 1) {
        int t = __shfl_up_sync(0xffffffffu, v, o);
        if (lane >= o) v += t;
    }
    __shared__ int ws[32];
    if (lane == 31) ws[wid] = v;
    __syncthreads();
    if (wid == 0) {
        int w = ws[lane];
        #pragma unroll
        for (int o = 1; o < 32; o <<= 1) {
            int t = __shfl_up_sync(0xffffffffu, w, o);
            if (lane >= o) w += t;
        }
        ws[lane] = w;
    }
    __syncthreads();
    if (wid > 0) v += ws[wid - 1];
    if (i < n) g_scantmp[i] = v;
    if (tid == 1023) g_bsums[blockIdx.x] = v;
}
// Parallel exclusive scan over block sums (nb <= 128), one 128-thread block.
__global__ void k_scan_sums(int nb) {
    int tid = threadIdx.x, lane = tid & 31, wid = tid >> 5;
    int orig = (tid < nb) ? g_bsums[tid] : 0;
    int v = orig;
    #pragma unroll
    for (int o = 1; o < 32; o <<= 1) {
        int t = __shfl_up_sync(0xffffffffu, v, o);
        if (lane >= o) v += t;
    }
    __shared__ int ws[4];
    if (lane == 31) ws[wid] = v;
    __syncthreads();
    int add = 0;
    #pragma unroll
    for (int w = 0; w < 4; w++)
        if (w < wid) add += ws[w];
    if (tid < nb) g_bsums[tid] = v + add - orig;   // exclusive
}
__global__ void k_finalize(int n) {
    int i = blockIdx.x * 1024 + threadIdx.x;
    if (i >= n) return;
    int incl = g_scantmp[i] + g_bsums[blockIdx.x];
    int d = g_deg[i];
    int excl = incl - d;
    g_cursor[i] = excl;
    g_rowptr[i] = excl;
    if (i == n - 1) g_rowptr[n] = incl;
    g_dinv[i] = rsqrtf((float)(d + 1));
}
__global__ void k_scatter(const int* __restrict__ src,
                          const int* __restrict__ dst, int e) {
    int i = blockIdx.x * blockDim.x + threadIdx.x;
    if (i < e) {
        int d = dst[i];
        int p = atomicAdd(&g_cursor[d], 1);
        g_col[p] = src[i];
    }
}

// ---------------- W prep: W[k][n] f32 -> Wt[n][k] bf16 hi/lo ---------------
__global__ void k_wconv(const float* __restrict__ W, int slot) {
    int idx = blockIdx.x * blockDim.x + threadIdx.x;
    if (idx >= 128 * 128) return;
    int n = idx >> 7, k = idx & 127;
    float w = W[(size_t)k * 128 + n];
    __nv_bfloat16 h = __float2bfloat16_rn(w);
    __nv_bfloat16 l = __float2bfloat16_rn(w - __bfloat162float(h));
    g_Wth[slot][n * 128 + k] = h;
    g_Wtl[slot][n * 128 + k] = l;
}

// ---------------- mma helper -----------------------------------------------
__device__ __forceinline__ void mma_bf16(float* c, const uint32_t* a,
                                         const uint32_t* b) {
    asm volatile(
        "mma.sync.aligned.m16n8k16.row.col.f32.bf16.bf16.f32 "
        "{%0,%1,%2,%3}, {%4,%5,%6,%7}, {%8,%9}, {%0,%1,%2,%3};"
        : "+f"(c[0]), "+f"(c[1]), "+f"(c[2]), "+f"(c[3])
        : "r"(a[0]), "r"(a[1]), "r"(a[2]), "r"(a[3]), "r"(b[0]), "r"(b[1]));
}

// ---------------- split-bf16 tensor GEMM: C[M,128] = A[M,128] @ W[128,128] --
// BM=128, BN=128, K chunked by 32. 256 threads = 8 warps, warp tile 32x64.
#define KP 40
template <int A_SEL>
__global__ void __launch_bounds__(256)
gemm128_mma_k(const float* __restrict__ Ap, int wslot, int M) {
    const float* __restrict__ A = (A_SEL == 0) ? Ap : (const float*)g_G;
    float* __restrict__ C = (float*)g_H;

    __shared__ __nv_bfloat16 Ash[128][KP];
    __shared__ __nv_bfloat16 Asl[128][KP];
    __shared__ __nv_bfloat16 Wsh[128][KP];
    __shared__ __nv_bfloat16 Wsl[128][KP];

    const int tid = threadIdx.x;
    const int wid = tid >> 5;
    const int lane = tid & 31;
    const int gid = lane >> 2;
    const int tig = lane & 3;
    const int mw = wid & 3;
    const int nw = wid >> 2;
    const int rowBase = blockIdx.x * 128;

    const int ar  = tid >> 1;
    const int akl = (tid & 1) * 16;
    const int wn  = tid >> 1;
    const int wkl = (tid & 1) * 16;

    float acc[2][8][4];
    #pragma unroll
    for (int i = 0; i < 2; i++)
        #pragma unroll
        for (int j = 0; j < 8; j++)
            #pragma unroll
            for (int q = 0; q < 4; q++) acc[i][j][q] = 0.f;

    const __nv_bfloat16* __restrict__ Wth = g_Wth[wslot];
    const __nv_bfloat16* __restrict__ Wtl = g_Wtl[wslot];

    for (int kt = 0; kt < 128; kt += 32) {
        // ---- stage A chunk (convert f32 -> bf16 hi/lo), 16 elems/thread
        {
            const int gr = rowBase + ar;
            const bool valid = (gr < M);
            #pragma unroll
            for (int j = 0; j < 4; j++) {
                float4 v = valid
                    ? *(const float4*)&A[(size_t)gr * 128 + kt + akl + j * 4]
                    : make_float4(0.f, 0.f, 0.f, 0.f);
                float f[4] = {v.x, v.y, v.z, v.w};
                #pragma unroll
                for (int q = 0; q < 4; q++) {
                    __nv_bfloat16 h = __float2bfloat16_rn(f[q]);
                    __nv_bfloat16 l =
                        __float2bfloat16_rn(f[q] - __bfloat162float(h));
                    Ash[ar][akl + j * 4 + q] = h;
                    Asl[ar][akl + j * 4 + q] = l;
                }
            }
        }
        // ---- stage W chunk (bf16 [n][k]): 16 elems/thread = 2 x uint4
        {
            const size_t base = (size_t)wn * 128 + kt + wkl;
            uint4 vh0 = *(const uint4*)&Wth[base];
            uint4 vh1 = *(const uint4*)&Wth[base + 8];
            uint4 vl0 = *(const uint4*)&Wtl[base];
            uint4 vl1 = *(const uint4*)&Wtl[base + 8];
            *(uint4*)&Wsh[wn][wkl]     = vh0;
            *(uint4*)&Wsh[wn][wkl + 8] = vh1;
            *(uint4*)&Wsl[wn][wkl]     = vl0;
            *(uint4*)&Wsl[wn][wkl + 8] = vl1;
        }
        __syncthreads();

        #pragma unroll
        for (int ks = 0; ks < 32; ks += 16) {
            uint32_t Ah[2][4], Al[2][4], Bh[8][2], Bl[8][2];
            #pragma unroll
            for (int mt = 0; mt < 2; mt++) {
                const int r = mw * 32 + mt * 16 + gid;
                Ah[mt][0] = *(const uint32_t*)&Ash[r][ks + tig * 2];
                Ah[mt][1] = *(const uint32_t*)&Ash[r + 8][ks + tig * 2];
                Ah[mt][2] = *(const uint32_t*)&Ash[r][ks + 8 + tig * 2];
                Ah[mt][3] = *(const uint32_t*)&Ash[r + 8][ks + 8 + tig * 2];
                Al[mt][0] = *(const uint32_t*)&Asl[r][ks + tig * 2];
                Al[mt][1] = *(const uint32_t*)&Asl[r + 8][ks + tig * 2];
                Al[mt][2] = *(const uint32_t*)&Asl[r][ks + 8 + tig * 2];
                Al[mt][3] = *(const uint32_t*)&Asl[r + 8][ks + 8 + tig * 2];
            }
            #pragma unroll
            for (int nt = 0; nt < 8; nt++) {
                const int nn = nw * 64 + nt * 8 + gid;
                Bh[nt][0] = *(const uint32_t*)&Wsh[nn][ks + tig * 2];
                Bh[nt][1] = *(const uint32_t*)&Wsh[nn][ks + 8 + tig * 2];
                Bl[nt][0] = *(const uint32_t*)&Wsl[nn][ks + tig * 2];
                Bl[nt][1] = *(const uint32_t*)&Wsl[nn][ks + 8 + tig * 2];
            }
            #pragma unroll
            for (int mt = 0; mt < 2; mt++)
                #pragma unroll
                for (int nt = 0; nt < 8; nt++)
                    mma_bf16(acc[mt][nt], Ah[mt], Bh[nt]);
            #pragma unroll
            for (int mt = 0; mt < 2; mt++)
                #pragma unroll
                for (int nt = 0; nt < 8; nt++)
                    mma_bf16(acc[mt][nt], Ah[mt], Bl[nt]);
            #pragma unroll
            for (int mt = 0; mt < 2; mt++)
                #pragma unroll
                for (int nt = 0; nt < 8; nt++)
                    mma_bf16(acc[mt][nt], Al[mt], Bh[nt]);
        }
        __syncthreads();
    }

    // ---- epilogue
    #pragma unroll
    for (int mt = 0; mt < 2; mt++) {
        const int r = rowBase + mw * 32 + mt * 16 + gid;
        #pragma unroll
        for (int nt = 0; nt < 8; nt++) {
            const int col = nw * 64 + nt * 8 + tig * 2;
            if (r < M)
                *(float2*)&C[(size_t)r * 128 + col] =
                    make_float2(acc[mt][nt][0], acc[mt][nt][1]);
            if (r + 8 < M)
                *(float2*)&C[(size_t)(r + 8) * 128 + col] =
                    make_float2(acc[mt][nt][2], acc[mt][nt][3]);
        }
    }
}

// ---------------- small GEMM for layer 3: C[M,40] = A[M,128] @ W[128,40] ----
__global__ void gemm40_k(const float* __restrict__ W, int M) {
    const float* __restrict__ A = (const float*)g_G;
    float* __restrict__ C = (float*)g_H;
    constexpr int BM = 64, BK = 32, K = 128, BN = 64, NA = 40;
    __shared__ float As[BM][BK];
    __shared__ float Ws[BK][BN];
    int tid = threadIdx.x;
    int tx = tid % 16;
    int ty = tid / 16;
    int rowBase = blockIdx.x * BM;

    float acc[4][4];
    #pragma unroll
    for (int i = 0; i < 4; i++)
        #pragma unroll
        for (int j = 0; j < 4; j++) acc[i][j] = 0.f;

    for (int kt = 0; kt < K; kt += BK) {
        #pragma unroll
        for (int t = 0; t < (BM * BK) / 256; t++) {
            int idx = tid + t * 256;
            int r = idx / BK, kk = idx % BK;
            int gr = rowBase + r;
            As[r][kk] = (gr < M) ? A[(size_t)gr * K + kt + kk] : 0.f;
        }
        #pragma unroll
        for (int t = 0; t < (BK * BN) / 256; t++) {
            int idx = tid + t * 256;
            int r = idx / BN, c = idx % BN;
            Ws[r][c] = (c < NA) ? W[(kt + r) * NA + c] : 0.f;
        }
        __syncthreads();
        #pragma unroll
        for (int kk = 0; kk < BK; kk++) {
            float b0 = Ws[kk][tx * 4 + 0];
            float b1 = Ws[kk][tx * 4 + 1];
            float b2 = Ws[kk][tx * 4 + 2];
            float b3 = Ws[kk][tx * 4 + 3];
            #pragma unroll
            for (int i = 0; i < 4; i++) {
                float a = As[ty * 4 + i][kk];
                acc[i][0] += a * b0;
                acc[i][1] += a * b1;
                acc[i][2] += a * b2;
                acc[i][3] += a * b3;
            }
        }
        __syncthreads();
    }
    #pragma unroll
    for (int i = 0; i < 4; i++) {
        int gr = rowBase + ty * 4 + i;
        if (gr >= M) continue;
        #pragma unroll
        for (int j = 0; j < 4; j++) {
            int c = tx * 4 + j;
            if (c < NA) C[(size_t)gr * NA + c] = acc[i][j];
        }
    }
}

// ---------------- aggregation, F=128 (one warp per node, 4-way MLP) --------
__global__ void agg128_k(const float* __restrict__ bias, int relu, int n) {
    int node = blockIdx.x * (blockDim.x >> 5) + (threadIdx.x >> 5);
    if (node >= n) return;
    int lane = threadIdx.x & 31;
    const float4* __restrict__ H4 = (const float4*)g_H;
    float* __restrict__ O = (float*)g_G;
    float di = g_dinv[node];
    float4 h = H4[(size_t)node * 32 + lane];
    float ax = di * h.x, ay = di * h.y, az = di * h.z, aw = di * h.w;
    int p = g_rowptr[node], pend = g_rowptr[node + 1];
    for (; p + 4 <= pend; p += 4) {
        int s0 = g_col[p], s1 = g_col[p + 1], s2 = g_col[p + 2], s3 = g_col[p + 3];
        float d0 = g_dinv[s0], d1 = g_dinv[s1], d2 = g_dinv[s2], d3 = g_dinv[s3];
        float4 h0 = H4[(size_t)s0 * 32 + lane];
        float4 h1 = H4[(size_t)s1 * 32 + lane];
        float4 h2 = H4[(size_t)s2 * 32 + lane];
        float4 h3 = H4[(size_t)s3 * 32 + lane];
        ax += d0 * h0.x; ay += d0 * h0.y; az += d0 * h0.z; aw += d0 * h0.w;
        ax += d1 * h1.x; ay += d1 * h1.y; az += d1 * h1.z; aw += d1 * h1.w;
        ax += d2 * h2.x; ay += d2 * h2.y; az += d2 * h2.z; aw += d2 * h2.w;
        ax += d3 * h3.x; ay += d3 * h3.y; az += d3 * h3.z; aw += d3 * h3.w;
    }
    for (; p < pend; p++) {
        int s = g_col[p];
        float ds = g_dinv[s];
        float4 hs = H4[(size_t)s * 32 + lane];
        ax += ds * hs.x; ay += ds * hs.y; az += ds * hs.z; aw += ds * hs.w;
    }
    float4 bv = ((const float4*)bias)[lane];
    float ox = di * ax + bv.x, oy = di * ay + bv.y;
    float oz = di * az + bv.z, ow = di * aw + bv.w;
    if (relu) {
        ox = fmaxf(ox, 0.f); oy = fmaxf(oy, 0.f);
        oz = fmaxf(oz, 0.f); ow = fmaxf(ow, 0.f);
    }
    ((float4*)O)[(size_t)node * 32 + lane] = make_float4(ox, oy, oz, ow);
}

// ---------------- aggregation, F=40 ----------------------------------------
__global__ void agg40_k(const float* __restrict__ bias, float* __restrict__ O, int n) {
    int node = blockIdx.x * (blockDim.x >> 5) + (threadIdx.x >> 5);
    if (node >= n) return;
    int lane = threadIdx.x & 31;
    const float* __restrict__ H = (const float*)g_H;
    bool hi = (lane < 8);
    float di = g_dinv[node];
    float a0 = di * H[(size_t)node * 40 + lane];
    float a1 = hi ? di * H[(size_t)node * 40 + 32 + lane] : 0.f;
    int p = g_rowptr[node], pend = g_rowptr[node + 1];
    for (; p + 2 <= pend; p += 2) {
        int s0 = g_col[p], s1 = g_col[p + 1];
        float d0 = g_dinv[s0], d1 = g_dinv[s1];
        a0 += d0 * H[(size_t)s0 * 40 + lane] + d1 * H[(size_t)s1 * 40 + lane];
        if (hi) {
            a1 += d0 * H[(size_t)s0 * 40 + 32 + lane];
            a1 += d1 * H[(size_t)s1 * 40 + 32 + lane];
        }
    }
    for (; p < pend; p++) {
        int s = g_col[p];
        float ds = g_dinv[s];
        a0 += ds * H[(size_t)s * 40 + lane];
        if (hi) a1 += ds * H[(size_t)s * 40 + 32 + lane];
    }
    O[(size_t)node * 40 + lane] = di * a0 + bias[lane];
    if (hi) O[(size_t)node * 40 + 32 + lane] = di * a1 + bias[32 + lane];
}

// ---------------- launch ----------------------------------------------------
// Launch order chosen so the heavy gemm128 lands in the ncu capture window
// (the profiler has been sampling the 4th launch every round).
extern "C" void kernel_launch(void* const* d_in, const int* in_sizes, int n_in,
                              void* d_out, int out_size) {
    const float* x   = (const float*)d_in[0];
    const int*   ei  = (const int*)d_in[1];    // int32 (JAX x64 disabled)
    const float* W1  = (const float*)d_in[2];
    const float* b1  = (const float*)d_in[3];
    const float* Wm  = (const float*)d_in[4];
    const float* bm  = (const float*)d_in[5];
    const float* W2  = (const float*)d_in[6];
    const float* b2  = (const float*)d_in[7];
    float* out = (float*)d_out;

    const int n = NN, e = NE;
    const int* src = ei;
    const int* dst = ei + e;

    const int scanBlocks = (n + 1023) / 1024;   // 98
    const int tcBlocks  = (n + 127) / 128;
    const int aggBlocks = (n + 7) / 8;

    // idx 0-2: weight conversion + zero (no deps)
    k_wconv<<<64, 256>>>(W1, 0);
    k_wconv<<<64, 256>>>(Wm, 1);
    k_zero_deg<<<(n + 255) / 256, 256>>>(n);

    // idx 3: layer-1 GEMM (depends only on wconv) — target of ncu window
    gemm128_mma_k<0><<<tcBlocks, 256>>>(x, 0, n);

    // graph prep (CSR build)
    k_count<<<(e + 255) / 256, 256>>>(dst, e);
    k_scan_block<<<scanBlocks, 1024>>>(n);
    k_scan_sums<<<1, 128>>>(scanBlocks);
    k_finalize<<<scanBlocks, 1024>>>(n);
    k_scatter<<<(e + 255) / 256, 256>>>(src, dst, e);

    // layer 1 agg
    agg128_k<<<aggBlocks, 256>>>(b1, 1, n);

    // layer 2
    gemm128_mma_k<1><<<tcBlocks, 256>>>(nullptr, 1, n);
    agg128_k<<<aggBlocks, 256>>>(bm, 1, n);

    // layer 3
    gemm40_k<<<(n + 63) / 64, 256>>>(W2, n);
    agg40_k<<<aggBlocks, 256>>>(b2, out, n);
}

// round 11
// speedup vs baseline: 1.4995x; 1.0538x over previous
#include <cuda_runtime.h>
#include <cuda_bf16.h>
#include <cstdint>

// Problem constants
#define NN 100000
#define NE 1600000

// ---------------- scratch (device globals) ----------------------------------
__device__ float g_H[(size_t)NN * 128];
__device__ float g_G[(size_t)NN * 128];
__device__ int   g_deg[NN];
__device__ int   g_rowptr[NN + 1];
__device__ int   g_cursor[NN];
__device__ int   g_col[NE];
__device__ float g_dinv[NN];
__device__ int   g_scantmp[NN];
__device__ int   g_bsums[128];
__device__ __nv_bfloat16 g_Wth[2][128 * 128];
__device__ __nv_bfloat16 g_Wtl[2][128 * 128];

// ---------------- graph prep -----------------------------------------------
__global__ void k_zero_deg(int n) {
    int i = blockIdx.x * blockDim.x + threadIdx.x;
    if (i < n) g_deg[i] = 0;
}
__global__ void k_count(const int* __restrict__ dst, int e) {
    int i = blockIdx.x * blockDim.x + threadIdx.x;
    if (i < e) atomicAdd(&g_deg[dst[i]], 1);
}
__global__ void k_scan_block(int n) {
    int tid = threadIdx.x, lane = tid & 31, wid = tid >> 5;
    int i = blockIdx.x * 1024 + tid;
    int v = (i < n) ? g_deg[i] : 0;
    #pragma unroll
    for (int o = 1; o < 32; o <<= 1) {
        int t = __shfl_up_sync(0xffffffffu, v, o);
        if (lane >= o) v += t;
    }
    __shared__ int ws[32];
    if (lane == 31) ws[wid] = v;
    __syncthreads();
    if (wid == 0) {
        int w = ws[lane];
        #pragma unroll
        for (int o = 1; o < 32; o <<= 1) {
            int t = __shfl_up_sync(0xffffffffu, w, o);
            if (lane >= o) w += t;
        }
        ws[lane] = w;
    }
    __syncthreads();
    if (wid > 0) v += ws[wid - 1];
    if (i < n) g_scantmp[i] = v;
    if (tid == 1023) g_bsums[blockIdx.x] = v;
}
__global__ void k_scan_sums(int nb) {
    int tid = threadIdx.x, lane = tid & 31, wid = tid >> 5;
    int orig = (tid < nb) ? g_bsums[tid] : 0;
    int v = orig;
    #pragma unroll
    for (int o = 1; o < 32; o <<= 1) {
        int t = __shfl_up_sync(0xffffffffu, v, o);
        if (lane >= o) v += t;
    }
    __shared__ int ws[4];
    if (lane == 31) ws[wid] = v;
    __syncthreads();
    int add = 0;
    #pragma unroll
    for (int w = 0; w < 4; w++)
        if (w < wid) add += ws[w];
    if (tid < nb) g_bsums[tid] = v + add - orig;
}
__global__ void k_finalize(int n) {
    int i = blockIdx.x * 1024 + threadIdx.x;
    if (i >= n) return;
    int incl = g_scantmp[i] + g_bsums[blockIdx.x];
    int d = g_deg[i];
    int excl = incl - d;
    g_cursor[i] = excl;
    g_rowptr[i] = excl;
    if (i == n - 1) g_rowptr[n] = incl;
    g_dinv[i] = rsqrtf((float)(d + 1));
}
__global__ void k_scatter(const int* __restrict__ src,
                          const int* __restrict__ dst, int e) {
    int i = blockIdx.x * blockDim.x + threadIdx.x;
    if (i < e) {
        int d = dst[i];
        int p = atomicAdd(&g_cursor[d], 1);
        g_col[p] = src[i];
    }
}

// ---------------- W prep ----------------------------------------------------
__global__ void k_wconv(const float* __restrict__ W, int slot) {
    int idx = blockIdx.x * blockDim.x + threadIdx.x;
    if (idx >= 128 * 128) return;
    int n = idx >> 7, k = idx & 127;
    float w = W[(size_t)k * 128 + n];
    __nv_bfloat16 h = __float2bfloat16_rn(w);
    __nv_bfloat16 l = __float2bfloat16_rn(w - __bfloat162float(h));
    g_Wth[slot][n * 128 + k] = h;
    g_Wtl[slot][n * 128 + k] = l;
}

// ---------------- mma / ldmatrix helpers ------------------------------------
__device__ __forceinline__ void mma_bf16(float* c, const uint32_t* a,
                                         const uint32_t* b) {
    asm volatile(
        "mma.sync.aligned.m16n8k16.row.col.f32.bf16.bf16.f32 "
        "{%0,%1,%2,%3}, {%4,%5,%6,%7}, {%8,%9}, {%0,%1,%2,%3};"
        : "+f"(c[0]), "+f"(c[1]), "+f"(c[2]), "+f"(c[3])
        : "r"(a[0]), "r"(a[1]), "r"(a[2]), "r"(a[3]), "r"(b[0]), "r"(b[1]));
}
__device__ __forceinline__ void ldm_x4(uint32_t& r0, uint32_t& r1,
                                       uint32_t& r2, uint32_t& r3,
                                       uint32_t addr) {
    asm volatile(
        "ldmatrix.sync.aligned.m8n8.x4.shared.b16 {%0,%1,%2,%3}, [%4];"
        : "=r"(r0), "=r"(r1), "=r"(r2), "=r"(r3) : "r"(addr));
}
__device__ __forceinline__ uint32_t smem_u32(const void* p) {
    uint32_t a;
    asm("{ .reg .u64 t; cvta.to.shared.u64 t, %1; cvt.u32.u64 %0, t; }"
        : "=r"(a) : "l"(p));
    return a;
}

// ---------------- split-bf16 tensor GEMM ------------------------------------
// C[M,128] = A[M,128] @ W[128,128]; 3-term split-bf16.
#define KP 40   // row pad (80 B): 5r mod 8 permutation -> ldmatrix conflict-free
template <int A_SEL>
__global__ void __launch_bounds__(256)
gemm128_mma_k(const float* __restrict__ Ap, int wslot, int M) {
    const float* __restrict__ A = (A_SEL == 0) ? Ap : (const float*)g_G;
    float* __restrict__ C = (float*)g_H;

    __shared__ __nv_bfloat16 Ash[128][KP];
    __shared__ __nv_bfloat16 Asl[128][KP];
    __shared__ __nv_bfloat16 Wsh[128][KP];
    __shared__ __nv_bfloat16 Wsl[128][KP];

    const int tid = threadIdx.x;
    const int wid = tid >> 5;
    const int lane = tid & 31;
    const int gid = lane >> 2;
    const int tig = lane & 3;
    const int mw = wid & 3;
    const int nw = wid >> 2;
    const int rowBase = blockIdx.x * 128;

    const int ar  = tid >> 1;
    const int akl = (tid & 1) * 16;
    const int wn  = tid >> 1;
    const int wkl = (tid & 1) * 16;

    // ldmatrix lane addressing
    const int lr = lane & 7;
    const int g8 = lane >> 3;               // 0..3
    // A: frag order [r, r+8, k+8 r, k+8 r+8]
    const int a_row = mw * 32 + (g8 & 1) * 8 + lr;
    const int a_col = (g8 >> 1) * 8;
    // B: frag order [n k, n k+8, n+8 k, n+8 k+8]
    const int b_row = nw * 64 + (g8 >> 1) * 8 + lr;
    const int b_col = (g8 & 1) * 8;

    const uint32_t ashb = smem_u32(&Ash[0][0]);
    const uint32_t aslb = smem_u32(&Asl[0][0]);
    const uint32_t wshb = smem_u32(&Wsh[0][0]);
    const uint32_t wslb = smem_u32(&Wsl[0][0]);

    float acc[2][8][4];
    #pragma unroll
    for (int i = 0; i < 2; i++)
        #pragma unroll
        for (int j = 0; j < 8; j++)
            #pragma unroll
            for (int q = 0; q < 4; q++) acc[i][j][q] = 0.f;

    const __nv_bfloat16* __restrict__ Wth = g_Wth[wslot];
    const __nv_bfloat16* __restrict__ Wtl = g_Wtl[wslot];

    for (int kt = 0; kt < 128; kt += 32) {
        // ---- stage A chunk: packed CVT + 2x STS.128 per array
        {
            const int gr = rowBase + ar;
            const bool valid = (gr < M);
            uint32_t hw[8], lw[8];
            #pragma unroll
            for (int j = 0; j < 4; j++) {
                float4 v = valid
                    ? *(const float4*)&A[(size_t)gr * 128 + kt + akl + j * 4]
                    : make_float4(0.f, 0.f, 0.f, 0.f);
                __nv_bfloat162 h0 = __float22bfloat162_rn(make_float2(v.x, v.y));
                __nv_bfloat162 h1 = __float22bfloat162_rn(make_float2(v.z, v.w));
                float2 hf0 = __bfloat1622float2(h0);
                float2 hf1 = __bfloat1622float2(h1);
                __nv_bfloat162 l0 = __float22bfloat162_rn(
                    make_float2(v.x - hf0.x, v.y - hf0.y));
                __nv_bfloat162 l1 = __float22bfloat162_rn(
                    make_float2(v.z - hf1.x, v.w - hf1.y));
                hw[j * 2 + 0] = *(uint32_t*)&h0;
                hw[j * 2 + 1] = *(uint32_t*)&h1;
                lw[j * 2 + 0] = *(uint32_t*)&l0;
                lw[j * 2 + 1] = *(uint32_t*)&l1;
            }
            *(uint4*)&Ash[ar][akl]     = make_uint4(hw[0], hw[1], hw[2], hw[3]);
            *(uint4*)&Ash[ar][akl + 8] = make_uint4(hw[4], hw[5], hw[6], hw[7]);
            *(uint4*)&Asl[ar][akl]     = make_uint4(lw[0], lw[1], lw[2], lw[3]);
            *(uint4*)&Asl[ar][akl + 8] = make_uint4(lw[4], lw[5], lw[6], lw[7]);
        }
        // ---- stage W chunk: 2x uint4 per array
        {
            const size_t base = (size_t)wn * 128 + kt + wkl;
            uint4 vh0 = *(const uint4*)&Wth[base];
            uint4 vh1 = *(const uint4*)&Wth[base + 8];
            uint4 vl0 = *(const uint4*)&Wtl[base];
            uint4 vl1 = *(const uint4*)&Wtl[base + 8];
            *(uint4*)&Wsh[wn][wkl]     = vh0;
            *(uint4*)&Wsh[wn][wkl + 8] = vh1;
            *(uint4*)&Wsl[wn][wkl]     = vl0;
            *(uint4*)&Wsl[wn][wkl + 8] = vl1;
        }
        __syncthreads();

        #pragma unroll
        for (int ks = 0; ks < 32; ks += 16) {
            uint32_t Ah[2][4], Al[2][4], Bh[8][2], Bl[8][2];
            // A fragments: one ldmatrix.x4 per (mt, hi/lo)
            #pragma unroll
            for (int mt = 0; mt < 2; mt++) {
                const uint32_t off =
                    (uint32_t)((a_row + mt * 16) * KP + ks + a_col) * 2;
                ldm_x4(Ah[mt][0], Ah[mt][1], Ah[mt][2], Ah[mt][3], ashb + off);
                ldm_x4(Al[mt][0], Al[mt][1], Al[mt][2], Al[mt][3], aslb + off);
            }
            // B fragments: one ldmatrix.x4 per (nt-pair, hi/lo)
            #pragma unroll
            for (int ntp = 0; ntp < 4; ntp++) {
                const uint32_t off =
                    (uint32_t)((b_row + ntp * 16) * KP + ks + b_col) * 2;
                ldm_x4(Bh[2 * ntp][0], Bh[2 * ntp][1],
                       Bh[2 * ntp + 1][0], Bh[2 * ntp + 1][1], wshb + off);
                ldm_x4(Bl[2 * ntp][0], Bl[2 * ntp][1],
                       Bl[2 * ntp + 1][0], Bl[2 * ntp + 1][1], wslb + off);
            }
            #pragma unroll
            for (int mt = 0; mt < 2; mt++)
                #pragma unroll
                for (int nt = 0; nt < 8; nt++)
                    mma_bf16(acc[mt][nt], Ah[mt], Bh[nt]);
            #pragma unroll
            for (int mt = 0; mt < 2; mt++)
                #pragma unroll
                for (int nt = 0; nt < 8; nt++)
                    mma_bf16(acc[mt][nt], Ah[mt], Bl[nt]);
            #pragma unroll
            for (int mt = 0; mt < 2; mt++)
                #pragma unroll
                for (int nt = 0; nt < 8; nt++)
                    mma_bf16(acc[mt][nt], Al[mt], Bh[nt]);
        }
        __syncthreads();
    }

    // ---- epilogue
    #pragma unroll
    for (int mt = 0; mt < 2; mt++) {
        const int r = rowBase + mw * 32 + mt * 16 + gid;
        #pragma unroll
        for (int nt = 0; nt < 8; nt++) {
            const int col = nw * 64 + nt * 8 + tig * 2;
            if (r < M)
                *(float2*)&C[(size_t)r * 128 + col] =
                    make_float2(acc[mt][nt][0], acc[mt][nt][1]);
            if (r + 8 < M)
                *(float2*)&C[(size_t)(r + 8) * 128 + col] =
                    make_float2(acc[mt][nt][2], acc[mt][nt][3]);
        }
    }
}

// ---------------- small GEMM for layer 3 ------------------------------------
__global__ void gemm40_k(const float* __restrict__ W, int M) {
    const float* __restrict__ A = (const float*)g_G;
    float* __restrict__ C = (float*)g_H;
    constexpr int BM = 64, BK = 32, K = 128, BN = 64, NA = 40;
    __shared__ float As[BM][BK];
    __shared__ float Ws[BK][BN];
    int tid = threadIdx.x;
    int tx = tid % 16;
    int ty = tid / 16;
    int rowBase = blockIdx.x * BM;

    float acc[4][4];
    #pragma unroll
    for (int i = 0; i < 4; i++)
        #pragma unroll
        for (int j = 0; j < 4; j++) acc[i][j] = 0.f;

    for (int kt = 0; kt < K; kt += BK) {
        #pragma unroll
        for (int t = 0; t < (BM * BK) / 256; t++) {
            int idx = tid + t * 256;
            int r = idx / BK, kk = idx % BK;
            int gr = rowBase + r;
            As[r][kk] = (gr < M) ? A[(size_t)gr * K + kt + kk] : 0.f;
        }
        #pragma unroll
        for (int t = 0; t < (BK * BN) / 256; t++) {
            int idx = tid + t * 256;
            int r = idx / BN, c = idx % BN;
            Ws[r][c] = (c < NA) ? W[(kt + r) * NA + c] : 0.f;
        }
        __syncthreads();
        #pragma unroll
        for (int kk = 0; kk < BK; kk++) {
            float b0 = Ws[kk][tx * 4 + 0];
            float b1 = Ws[kk][tx * 4 + 1];
            float b2 = Ws[kk][tx * 4 + 2];
            float b3 = Ws[kk][tx * 4 + 3];
            #pragma unroll
            for (int i = 0; i < 4; i++) {
                float a = As[ty * 4 + i][kk];
                acc[i][0] += a * b0;
                acc[i][1] += a * b1;
                acc[i][2] += a * b2;
                acc[i][3] += a * b3;
            }
        }
        __syncthreads();
    }
    #pragma unroll
    for (int i = 0; i < 4; i++) {
        int gr = rowBase + ty * 4 + i;
        if (gr >= M) continue;
        #pragma unroll
        for (int j = 0; j < 4; j++) {
            int c = tx * 4 + j;
            if (c < NA) C[(size_t)gr * NA + c] = acc[i][j];
        }
    }
}

// ---------------- aggregation, F=128 ----------------------------------------
__global__ void agg128_k(const float* __restrict__ bias, int relu, int n) {
    int node = blockIdx.x * (blockDim.x >> 5) + (threadIdx.x >> 5);
    if (node >= n) return;
    int lane = threadIdx.x & 31;
    const float4* __restrict__ H4 = (const float4*)g_H;
    float* __restrict__ O = (float*)g_G;
    float di = g_dinv[node];
    float4 h = H4[(size_t)node * 32 + lane];
    float ax = di * h.x, ay = di * h.y, az = di * h.z, aw = di * h.w;
    int p = g_rowptr[node], pend = g_rowptr[node + 1];
    for (; p + 4 <= pend; p += 4) {
        int s0 = g_col[p], s1 = g_col[p + 1], s2 = g_col[p + 2], s3 = g_col[p + 3];
        float d0 = g_dinv[s0], d1 = g_dinv[s1], d2 = g_dinv[s2], d3 = g_dinv[s3];
        float4 h0 = H4[(size_t)s0 * 32 + lane];
        float4 h1 = H4[(size_t)s1 * 32 + lane];
        float4 h2 = H4[(size_t)s2 * 32 + lane];
        float4 h3 = H4[(size_t)s3 * 32 + lane];
        ax += d0 * h0.x; ay += d0 * h0.y; az += d0 * h0.z; aw += d0 * h0.w;
        ax += d1 * h1.x; ay += d1 * h1.y; az += d1 * h1.z; aw += d1 * h1.w;
        ax += d2 * h2.x; ay += d2 * h2.y; az += d2 * h2.z; aw += d2 * h2.w;
        ax += d3 * h3.x; ay += d3 * h3.y; az += d3 * h3.z; aw += d3 * h3.w;
    }
    for (; p < pend; p++) {
        int s = g_col[p];
        float ds = g_dinv[s];
        float4 hs = H4[(size_t)s * 32 + lane];
        ax += ds * hs.x; ay += ds * hs.y; az += ds * hs.z; aw += ds * hs.w;
    }
    float4 bv = ((const float4*)bias)[lane];
    float ox = di * ax + bv.x, oy = di * ay + bv.y;
    float oz = di * az + bv.z, ow = di * aw + bv.w;
    if (relu) {
        ox = fmaxf(ox, 0.f); oy = fmaxf(oy, 0.f);
        oz = fmaxf(oz, 0.f); ow = fmaxf(ow, 0.f);
    }
    ((float4*)O)[(size_t)node * 32 + lane] = make_float4(ox, oy, oz, ow);
}

// ---------------- aggregation, F=40 ----------------------------------------
__global__ void agg40_k(const float* __restrict__ bias, float* __restrict__ O, int n) {
    int node = blockIdx.x * (blockDim.x >> 5) + (threadIdx.x >> 5);
    if (node >= n) return;
    int lane = threadIdx.x & 31;
    const float* __restrict__ H = (const float*)g_H;
    bool hi = (lane < 8);
    float di = g_dinv[node];
    float a0 = di * H[(size_t)node * 40 + lane];
    float a1 = hi ? di * H[(size_t)node * 40 + 32 + lane] : 0.f;
    int p = g_rowptr[node], pend = g_rowptr[node + 1];
    for (; p + 2 <= pend; p += 2) {
        int s0 = g_col[p], s1 = g_col[p + 1];
        float d0 = g_dinv[s0], d1 = g_dinv[s1];
        a0 += d0 * H[(size_t)s0 * 40 + lane] + d1 * H[(size_t)s1 * 40 + lane];
        if (hi) {
            a1 += d0 * H[(size_t)s0 * 40 + 32 + lane];
            a1 += d1 * H[(size_t)s1 * 40 + 32 + lane];
        }
    }
    for (; p < pend; p++) {
        int s = g_col[p];
        float ds = g_dinv[s];
        a0 += ds * H[(size_t)s * 40 + lane];
        if (hi) a1 += ds * H[(size_t)s * 40 + 32 + lane];
    }
    O[(size_t)node * 40 + lane] = di * a0 + bias[lane];
    if (hi) O[(size_t)node * 40 + 32 + lane] = di * a1 + bias[32 + lane];
}

// ---------------- launch ----------------------------------------------------
extern "C" void kernel_launch(void* const* d_in, const int* in_sizes, int n_in,
                              void* d_out, int out_size) {
    const float* x   = (const float*)d_in[0];
    const int*   ei  = (const int*)d_in[1];
    const float* W1  = (const float*)d_in[2];
    const float* b1  = (const float*)d_in[3];
    const float* Wm  = (const float*)d_in[4];
    const float* bm  = (const float*)d_in[5];
    const float* W2  = (const float*)d_in[6];
    const float* b2  = (const float*)d_in[7];
    float* out = (float*)d_out;

    const int n = NN, e = NE;
    const int* src = ei;
    const int* dst = ei + e;

    const int scanBlocks = (n + 1023) / 1024;
    const int tcBlocks  = (n + 127) / 128;
    const int aggBlocks = (n + 7) / 8;

    // idx 0-2: no-dep kernels
    k_wconv<<<64, 256>>>(W1, 0);
    k_wconv<<<64, 256>>>(Wm, 1);
    k_zero_deg<<<(n + 255) / 256, 256>>>(n);

    // idx 3: layer-1 GEMM — ncu capture window
    gemm128_mma_k<0><<<tcBlocks, 256>>>(x, 0, n);

    // graph prep (CSR build)
    k_count<<<(e + 255) / 256, 256>>>(dst, e);
    k_scan_block<<<scanBlocks, 1024>>>(n);
    k_scan_sums<<<1, 128>>>(scanBlocks);
    k_finalize<<<scanBlocks, 1024>>>(n);
    k_scatter<<<(e + 255) / 256, 256>>>(src, dst, e);

    // layer 1 agg
    agg128_k<<<aggBlocks, 256>>>(b1, 1, n);

    // layer 2
    gemm128_mma_k<1><<<tcBlocks, 256>>>(nullptr, 1, n);
    agg128_k<<<aggBlocks, 256>>>(bm, 1, n);

    // layer 3
    gemm40_k<<<(n + 63) / 64, 256>>>(W2, n);
    agg40_k<<<aggBlocks, 256>>>(b2, out, n);
}

// round 12
// speedup vs baseline: 1.5607x; 1.0408x over previous
#include <cuda_runtime.h>
#include <cuda_bf16.h>
#include <cstdint>

// Problem constants
#define NN 100000
#define NE 1600000

// ---------------- scratch (device globals) ----------------------------------
__device__ float g_H[(size_t)NN * 128];
__device__ float g_G[(size_t)NN * 128];
__device__ int   g_deg[NN];
__device__ int   g_rowptr[NN + 1];
__device__ int   g_cursor[NN];
__device__ int   g_col[NE];
__device__ float g_dinv[NN];
__device__ int   g_scantmp[NN];
__device__ int   g_bsums[128];
__device__ __nv_bfloat16 g_Wth[2][128 * 128];
__device__ __nv_bfloat16 g_Wtl[2][128 * 128];

// ---------------- graph prep -----------------------------------------------
__global__ void k_zero_deg(int n) {
    int i = blockIdx.x * blockDim.x + threadIdx.x;
    if (i < n) g_deg[i] = 0;
}
__global__ void k_count(const int* __restrict__ dst, int e) {
    int i = blockIdx.x * blockDim.x + threadIdx.x;
    if (i < e) atomicAdd(&g_deg[dst[i]], 1);
}
__global__ void k_scan_block(int n) {
    int tid = threadIdx.x, lane = tid & 31, wid = tid >> 5;
    int i = blockIdx.x * 1024 + tid;
    int v = (i < n) ? g_deg[i] : 0;
    #pragma unroll
    for (int o = 1; o < 32; o <<= 1) {
        int t = __shfl_up_sync(0xffffffffu, v, o);
        if (lane >= o) v += t;
    }
    __shared__ int ws[32];
    if (lane == 31) ws[wid] = v;
    __syncthreads();
    if (wid == 0) {
        int w = ws[lane];
        #pragma unroll
        for (int o = 1; o < 32; o <<= 1) {
            int t = __shfl_up_sync(0xffffffffu, w, o);
            if (lane >= o) w += t;
        }
        ws[lane] = w;
    }
    __syncthreads();
    if (wid > 0) v += ws[wid - 1];
    if (i < n) g_scantmp[i] = v;
    if (tid == 1023) g_bsums[blockIdx.x] = v;
}
__global__ void k_scan_sums(int nb) {
    int tid = threadIdx.x, lane = tid & 31, wid = tid >> 5;
    int orig = (tid < nb) ? g_bsums[tid] : 0;
    int v = orig;
    #pragma unroll
    for (int o = 1; o < 32; o <<= 1) {
        int t = __shfl_up_sync(0xffffffffu, v, o);
        if (lane >= o) v += t;
    }
    __shared__ int ws[4];
    if (lane == 31) ws[wid] = v;
    __syncthreads();
    int add = 0;
    #pragma unroll
    for (int w = 0; w < 4; w++)
        if (w < wid) add += ws[w];
    if (tid < nb) g_bsums[tid] = v + add - orig;
}
__global__ void k_finalize(int n) {
    int i = blockIdx.x * 1024 + threadIdx.x;
    if (i >= n) return;
    int incl = g_scantmp[i] + g_bsums[blockIdx.x];
    int d = g_deg[i];
    int excl = incl - d;
    g_cursor[i] = excl;
    g_rowptr[i] = excl;
    if (i == n - 1) g_rowptr[n] = incl;
    g_dinv[i] = rsqrtf((float)(d + 1));
}
__global__ void k_scatter(const int* __restrict__ src,
                          const int* __restrict__ dst, int e) {
    int i = blockIdx.x * blockDim.x + threadIdx.x;
    if (i < e) {
        int d = dst[i];
        int p = atomicAdd(&g_cursor[d], 1);
        g_col[p] = src[i];
    }
}

// ---------------- W prep ----------------------------------------------------
__global__ void k_wconv(const float* __restrict__ W, int slot) {
    int idx = blockIdx.x * blockDim.x + threadIdx.x;
    if (idx >= 128 * 128) return;
    int n = idx >> 7, k = idx & 127;
    float w = W[(size_t)k * 128 + n];
    __nv_bfloat16 h = __float2bfloat16_rn(w);
    __nv_bfloat16 l = __float2bfloat16_rn(w - __bfloat162float(h));
    g_Wth[slot][n * 128 + k] = h;
    g_Wtl[slot][n * 128 + k] = l;
}

// ---------------- mma / ldmatrix / cp.async helpers --------------------------
__device__ __forceinline__ void mma_bf16(float* c, const uint32_t* a,
                                         const uint32_t* b) {
    asm volatile(
        "mma.sync.aligned.m16n8k16.row.col.f32.bf16.bf16.f32 "
        "{%0,%1,%2,%3}, {%4,%5,%6,%7}, {%8,%9}, {%0,%1,%2,%3};"
        : "+f"(c[0]), "+f"(c[1]), "+f"(c[2]), "+f"(c[3])
        : "r"(a[0]), "r"(a[1]), "r"(a[2]), "r"(a[3]), "r"(b[0]), "r"(b[1]));
}
__device__ __forceinline__ void ldm_x4(uint32_t& r0, uint32_t& r1,
                                       uint32_t& r2, uint32_t& r3,
                                       uint32_t addr) {
    asm volatile(
        "ldmatrix.sync.aligned.m8n8.x4.shared.b16 {%0,%1,%2,%3}, [%4];"
        : "=r"(r0), "=r"(r1), "=r"(r2), "=r"(r3) : "r"(addr));
}
__device__ __forceinline__ uint32_t smem_u32(const void* p) {
    uint32_t a;
    asm("{ .reg .u64 t; cvta.to.shared.u64 t, %1; cvt.u32.u64 %0, t; }"
        : "=r"(a) : "l"(p));
    return a;
}
__device__ __forceinline__ void cp_async16(uint32_t saddr, const void* gptr) {
    asm volatile("cp.async.ca.shared.global [%0], [%1], 16;"
                 :: "r"(saddr), "l"(gptr) : "memory");
}
#define CP_COMMIT() asm volatile("cp.async.commit_group;" ::: "memory")
#define CP_WAIT0()  asm volatile("cp.async.wait_group 0;" ::: "memory")

// ---------------- pipelined split-bf16 tensor GEMM ---------------------------
// C[M,128] = A[M,128] @ W[128,128]; 3-term split-bf16.
// Dynamic smem layout (bytes): Ash 0, Asl 10240, Wsh[b] 20480+b*20480,
// Wsl[b] = Wsh[b]+10240. Total 61440 B.
#define KP 40
#define ARRB 10240u
template <int A_SEL>
__global__ void __launch_bounds__(256, 2)
gemm128_mma_k(const float* __restrict__ Ap, int wslot, int M) {
    const float* __restrict__ A = (A_SEL == 0) ? Ap : (const float*)g_G;
    float* __restrict__ C = (float*)g_H;
    extern __shared__ char dyns[];

    const int tid = threadIdx.x;
    const int wid = tid >> 5;
    const int lane = tid & 31;
    const int gid = lane >> 2;
    const int tig = lane & 3;
    const int mw = wid & 3;
    const int nw = wid >> 2;
    const int rowBase = blockIdx.x * 128;

    const int ar  = tid >> 1;
    const int akl = (tid & 1) * 16;
    const int wn  = tid >> 1;
    const int wkl = (tid & 1) * 16;

    // ldmatrix lane addressing (proven in R11)
    const int lr = lane & 7;
    const int g8 = lane >> 3;
    const int a_row = mw * 32 + (g8 & 1) * 8 + lr;
    const int a_col = (g8 >> 1) * 8;
    const int b_row = nw * 64 + (g8 >> 1) * 8 + lr;
    const int b_col = (g8 & 1) * 8;

    const uint32_t sbase = smem_u32(dyns);
    const uint32_t ashb = sbase;
    const uint32_t aslb = sbase + ARRB;

    const int gr = rowBase + ar;
    const bool valid = (gr < M);

    const __nv_bfloat16* __restrict__ Wth = g_Wth[wslot];
    const __nv_bfloat16* __restrict__ Wtl = g_Wtl[wslot];

    float acc[2][8][4];
    #pragma unroll
    for (int i = 0; i < 2; i++)
        #pragma unroll
        for (int j = 0; j < 8; j++)
            #pragma unroll
            for (int q = 0; q < 4; q++) acc[i][j][q] = 0.f;

    // ---- helpers ----
    auto ldg_A = [&](int kt, float4* v) {
        #pragma unroll
        for (int j = 0; j < 4; j++)
            v[j] = valid
                ? *(const float4*)&A[(size_t)gr * 128 + kt + akl + j * 4]
                : make_float4(0.f, 0.f, 0.f, 0.f);
    };
    auto cvt_sts_A = [&](const float4* v) {
        uint32_t hw[8], lw[8];
        #pragma unroll
        for (int j = 0; j < 4; j++) {
            __nv_bfloat162 h0 = __float22bfloat162_rn(make_float2(v[j].x, v[j].y));
            __nv_bfloat162 h1 = __float22bfloat162_rn(make_float2(v[j].z, v[j].w));
            float2 hf0 = __bfloat1622float2(h0);
            float2 hf1 = __bfloat1622float2(h1);
            __nv_bfloat162 l0 = __float22bfloat162_rn(
                make_float2(v[j].x - hf0.x, v[j].y - hf0.y));
            __nv_bfloat162 l1 = __float22bfloat162_rn(
                make_float2(v[j].z - hf1.x, v[j].w - hf1.y));
            hw[j * 2 + 0] = *(uint32_t*)&h0;
            hw[j * 2 + 1] = *(uint32_t*)&h1;
            lw[j * 2 + 0] = *(uint32_t*)&l0;
            lw[j * 2 + 1] = *(uint32_t*)&l1;
        }
        char* a0 = dyns + (ar * KP + akl) * 2;
        *(uint4*)(a0)            = make_uint4(hw[0], hw[1], hw[2], hw[3]);
        *(uint4*)(a0 + 16)       = make_uint4(hw[4], hw[5], hw[6], hw[7]);
        *(uint4*)(a0 + ARRB)     = make_uint4(lw[0], lw[1], lw[2], lw[3]);
        *(uint4*)(a0 + ARRB + 16)= make_uint4(lw[4], lw[5], lw[6], lw[7]);
    };
    auto stage_W = [&](int kt, int buf) {
        const size_t gbase = (size_t)wn * 128 + kt + wkl;
        const uint32_t s = sbase + 20480u + (uint32_t)buf * 20480u +
                           (uint32_t)(wn * KP + wkl) * 2;
        cp_async16(s,            &Wth[gbase]);
        cp_async16(s + 16,       &Wth[gbase + 8]);
        cp_async16(s + ARRB,     &Wtl[gbase]);
        cp_async16(s + ARRB + 16,&Wtl[gbase + 8]);
    };

    // ---- prologue: chunk 0 into buffer 0
    {
        float4 av[4];
        ldg_A(0, av);
        stage_W(0, 0);
        CP_COMMIT();
        cvt_sts_A(av);
        CP_WAIT0();
    }
    __syncthreads();

    // ---- main loop
    #pragma unroll
    for (int kt = 0; kt < 4; kt++) {
        const int b = kt & 1;
        float4 av[4];
        if (kt < 3) {
            ldg_A((kt + 1) * 32, av);
            stage_W((kt + 1) * 32, 1 - b);
            CP_COMMIT();
        }
        // mma over Ash (single buffer) + W buffer b
        const uint32_t wshb = sbase + 20480u + (uint32_t)b * 20480u;
        const uint32_t wslb = wshb + ARRB;
        #pragma unroll
        for (int ks = 0; ks < 32; ks += 16) {
            uint32_t Ah[2][4], Al[2][4];
            #pragma unroll
            for (int mt = 0; mt < 2; mt++) {
                const uint32_t off =
                    (uint32_t)((a_row + mt * 16) * KP + ks + a_col) * 2;
                ldm_x4(Ah[mt][0], Ah[mt][1], Ah[mt][2], Ah[mt][3], ashb + off);
                ldm_x4(Al[mt][0], Al[mt][1], Al[mt][2], Al[mt][3], aslb + off);
            }
            #pragma unroll
            for (int ntp = 0; ntp < 4; ntp++) {
                uint32_t Bh[2][2], Bl[2][2];
                const uint32_t off =
                    (uint32_t)((b_row + ntp * 16) * KP + ks + b_col) * 2;
                ldm_x4(Bh[0][0], Bh[0][1], Bh[1][0], Bh[1][1], wshb + off);
                ldm_x4(Bl[0][0], Bl[0][1], Bl[1][0], Bl[1][1], wslb + off);
                #pragma unroll
                for (int mt = 0; mt < 2; mt++)
                    #pragma unroll
                    for (int j = 0; j < 2; j++)
                        mma_bf16(acc[mt][2 * ntp + j], Ah[mt], Bh[j]);
                #pragma unroll
                for (int mt = 0; mt < 2; mt++)
                    #pragma unroll
                    for (int j = 0; j < 2; j++)
                        mma_bf16(acc[mt][2 * ntp + j], Ah[mt], Bl[j]);
                #pragma unroll
                for (int mt = 0; mt < 2; mt++)
                    #pragma unroll
                    for (int j = 0; j < 2; j++)
                        mma_bf16(acc[mt][2 * ntp + j], Al[mt], Bh[j]);
            }
        }
        __syncthreads();          // all warps done reading Ash
        if (kt < 3) {
            cvt_sts_A(av);        // write next A chunk
            CP_WAIT0();           // next W chunk landed
        }
        __syncthreads();
    }

    // ---- epilogue
    #pragma unroll
    for (int mt = 0; mt < 2; mt++) {
        const int r = rowBase + mw * 32 + mt * 16 + gid;
        #pragma unroll
        for (int nt = 0; nt < 8; nt++) {
            const int col = nw * 64 + nt * 8 + tig * 2;
            if (r < M)
                *(float2*)&C[(size_t)r * 128 + col] =
                    make_float2(acc[mt][nt][0], acc[mt][nt][1]);
            if (r + 8 < M)
                *(float2*)&C[(size_t)(r + 8) * 128 + col] =
                    make_float2(acc[mt][nt][2], acc[mt][nt][3]);
        }
    }
}

// ---------------- small GEMM for layer 3 ------------------------------------
__global__ void gemm40_k(const float* __restrict__ W, int M) {
    const float* __restrict__ A = (const float*)g_G;
    float* __restrict__ C = (float*)g_H;
    constexpr int BM = 64, BK = 32, K = 128, BN = 64, NA = 40;
    __shared__ float As[BM][BK];
    __shared__ float Ws[BK][BN];
    int tid = threadIdx.x;
    int tx = tid % 16;
    int ty = tid / 16;
    int rowBase = blockIdx.x * BM;

    float acc[4][4];
    #pragma unroll
    for (int i = 0; i < 4; i++)
        #pragma unroll
        for (int j = 0; j < 4; j++) acc[i][j] = 0.f;

    for (int kt = 0; kt < K; kt += BK) {
        #pragma unroll
        for (int t = 0; t < (BM * BK) / 256; t++) {
            int idx = tid + t * 256;
            int r = idx / BK, kk = idx % BK;
            int gr = rowBase + r;
            As[r][kk] = (gr < M) ? A[(size_t)gr * K + kt + kk] : 0.f;
        }
        #pragma unroll
        for (int t = 0; t < (BK * BN) / 256; t++) {
            int idx = tid + t * 256;
            int r = idx / BN, c = idx % BN;
            Ws[r][c] = (c < NA) ? W[(kt + r) * NA + c] : 0.f;
        }
        __syncthreads();
        #pragma unroll
        for (int kk = 0; kk < BK; kk++) {
            float b0 = Ws[kk][tx * 4 + 0];
            float b1 = Ws[kk][tx * 4 + 1];
            float b2 = Ws[kk][tx * 4 + 2];
            float b3 = Ws[kk][tx * 4 + 3];
            #pragma unroll
            for (int i = 0; i < 4; i++) {
                float a = As[ty * 4 + i][kk];
                acc[i][0] += a * b0;
                acc[i][1] += a * b1;
                acc[i][2] += a * b2;
                acc[i][3] += a * b3;
            }
        }
        __syncthreads();
    }
    #pragma unroll
    for (int i = 0; i < 4; i++) {
        int gr = rowBase + ty * 4 + i;
        if (gr >= M) continue;
        #pragma unroll
        for (int j = 0; j < 4; j++) {
            int c = tx * 4 + j;
            if (c < NA) C[(size_t)gr * NA + c] = acc[i][j];
        }
    }
}

// ---------------- aggregation, F=128 ----------------------------------------
__global__ void agg128_k(const float* __restrict__ bias, int relu, int n) {
    int node = blockIdx.x * (blockDim.x >> 5) + (threadIdx.x >> 5);
    if (node >= n) return;
    int lane = threadIdx.x & 31;
    const float4* __restrict__ H4 = (const float4*)g_H;
    float* __restrict__ O = (float*)g_G;
    float di = g_dinv[node];
    float4 h = H4[(size_t)node * 32 + lane];
    float ax = di * h.x, ay = di * h.y, az = di * h.z, aw = di * h.w;
    int p = g_rowptr[node], pend = g_rowptr[node + 1];
    for (; p + 4 <= pend; p += 4) {
        int s0 = g_col[p], s1 = g_col[p + 1], s2 = g_col[p + 2], s3 = g_col[p + 3];
        float d0 = g_dinv[s0], d1 = g_dinv[s1], d2 = g_dinv[s2], d3 = g_dinv[s3];
        float4 h0 = H4[(size_t)s0 * 32 + lane];
        float4 h1 = H4[(size_t)s1 * 32 + lane];
        float4 h2 = H4[(size_t)s2 * 32 + lane];
        float4 h3 = H4[(size_t)s3 * 32 + lane];
        ax += d0 * h0.x; ay += d0 * h0.y; az += d0 * h0.z; aw += d0 * h0.w;
        ax += d1 * h1.x; ay += d1 * h1.y; az += d1 * h1.z; aw += d1 * h1.w;
        ax += d2 * h2.x; ay += d2 * h2.y; az += d2 * h2.z; aw += d2 * h2.w;
        ax += d3 * h3.x; ay += d3 * h3.y; az += d3 * h3.z; aw += d3 * h3.w;
    }
    for (; p < pend; p++) {
        int s = g_col[p];
        float ds = g_dinv[s];
        float4 hs = H4[(size_t)s * 32 + lane];
        ax += ds * hs.x; ay += ds * hs.y; az += ds * hs.z; aw += ds * hs.w;
    }
    float4 bv = ((const float4*)bias)[lane];
    float ox = di * ax + bv.x, oy = di * ay + bv.y;
    float oz = di * az + bv.z, ow = di * aw + bv.w;
    if (relu) {
        ox = fmaxf(ox, 0.f); oy = fmaxf(oy, 0.f);
        oz = fmaxf(oz, 0.f); ow = fmaxf(ow, 0.f);
    }
    ((float4*)O)[(size_t)node * 32 + lane] = make_float4(ox, oy, oz, ow);
}

// ---------------- aggregation, F=40 ----------------------------------------
__global__ void agg40_k(const float* __restrict__ bias, float* __restrict__ O, int n) {
    int node = blockIdx.x * (blockDim.x >> 5) + (threadIdx.x >> 5);
    if (node >= n) return;
    int lane = threadIdx.x & 31;
    const float* __restrict__ H = (const float*)g_H;
    bool hi = (lane < 8);
    float di = g_dinv[node];
    float a0 = di * H[(size_t)node * 40 + lane];
    float a1 = hi ? di * H[(size_t)node * 40 + 32 + lane] : 0.f;
    int p = g_rowptr[node], pend = g_rowptr[node + 1];
    for (; p + 2 <= pend; p += 2) {
        int s0 = g_col[p], s1 = g_col[p + 1];
        float d0 = g_dinv[s0], d1 = g_dinv[s1];
        a0 += d0 * H[(size_t)s0 * 40 + lane] + d1 * H[(size_t)s1 * 40 + lane];
        if (hi) {
            a1 += d0 * H[(size_t)s0 * 40 + 32 + lane];
            a1 += d1 * H[(size_t)s1 * 40 + 32 + lane];
        }
    }
    for (; p < pend; p++) {
        int s = g_col[p];
        float ds = g_dinv[s];
        a0 += ds * H[(size_t)s * 40 + lane];
        if (hi) a1 += ds * H[(size_t)s * 40 + 32 + lane];
    }
    O[(size_t)node * 40 + lane] = di * a0 + bias[lane];
    if (hi) O[(size_t)node * 40 + 32 + lane] = di * a1 + bias[32 + lane];
}

// ---------------- launch ----------------------------------------------------
extern "C" void kernel_launch(void* const* d_in, const int* in_sizes, int n_in,
                              void* d_out, int out_size) {
    const float* x   = (const float*)d_in[0];
    const int*   ei  = (const int*)d_in[1];
    const float* W1  = (const float*)d_in[2];
    const float* b1  = (const float*)d_in[3];
    const float* Wm  = (const float*)d_in[4];
    const float* bm  = (const float*)d_in[5];
    const float* W2  = (const float*)d_in[6];
    const float* b2  = (const float*)d_in[7];
    float* out = (float*)d_out;

    const int n = NN, e = NE;
    const int* src = ei;
    const int* dst = ei + e;

    const int scanBlocks = (n + 1023) / 1024;
    const int tcBlocks  = (n + 127) / 128;
    const int aggBlocks = (n + 7) / 8;
    const int DSMEM = 61440;

    // opt-in to >48KB dynamic smem (idempotent; non-stream, non-allocating)
    cudaFuncSetAttribute(gemm128_mma_k<0>,
                         cudaFuncAttributeMaxDynamicSharedMemorySize, DSMEM);
    cudaFuncSetAttribute(gemm128_mma_k<1>,
                         cudaFuncAttributeMaxDynamicSharedMemorySize, DSMEM);

    // idx 0-2: no-dep kernels
    k_wconv<<<64, 256>>>(W1, 0);
    k_wconv<<<64, 256>>>(Wm, 1);
    k_zero_deg<<<(n + 255) / 256, 256>>>(n);

    // idx 3: layer-1 GEMM — ncu capture window
    gemm128_mma_k<0><<<tcBlocks, 256, DSMEM>>>(x, 0, n);

    // graph prep (CSR build)
    k_count<<<(e + 255) / 256, 256>>>(dst, e);
    k_scan_block<<<scanBlocks, 1024>>>(n);
    k_scan_sums<<<1, 128>>>(scanBlocks);
    k_finalize<<<scanBlocks, 1024>>>(n);
    k_scatter<<<(e + 255) / 256, 256>>>(src, dst, e);

    // layer 1 agg
    agg128_k<<<aggBlocks, 256>>>(b1, 1, n);

    // layer 2
    gemm128_mma_k<1><<<tcBlocks, 256, DSMEM>>>(nullptr, 1, n);
    agg128_k<<<aggBlocks, 256>>>(bm, 1, n);

    // layer 3
    gemm40_k<<<(n + 63) / 64, 256>>>(W2, n);
    agg40_k<<<aggBlocks, 256>>>(b2, out, n);
}

// round 13
// speedup vs baseline: 1.6091x; 1.0310x over previous
#include <cuda_runtime.h>
#include <cuda_bf16.h>
#include <cstdint>

// Problem constants
#define NN 100000
#define NE 1600000

// ---------------- scratch (device globals) ----------------------------------
__device__ float g_H[(size_t)NN * 128];
__device__ float g_G[(size_t)NN * 128];
__device__ int   g_deg[NN];
__device__ int   g_rowptr[NN + 1];
__device__ int   g_cursor[NN];
__device__ int   g_col[NE];
__device__ float g_dinv[NN];
__device__ int   g_scantmp[NN];
__device__ int   g_bsums[128];
__device__ __nv_bfloat16 g_Wth[2][128 * 128];
__device__ __nv_bfloat16 g_Wtl[2][128 * 128];

// ---------------- graph prep -----------------------------------------------
__global__ void k_zero_deg(int n) {
    int i = blockIdx.x * blockDim.x + threadIdx.x;
    if (i < n) g_deg[i] = 0;
}
__global__ void k_count(const int* __restrict__ dst, int e) {
    int i = blockIdx.x * blockDim.x + threadIdx.x;
    if (i < e) atomicAdd(&g_deg[dst[i]], 1);
}
__global__ void k_scan_block(int n) {
    int tid = threadIdx.x, lane = tid & 31, wid = tid >> 5;
    int i = blockIdx.x * 1024 + tid;
    int v = (i < n) ? g_deg[i] : 0;
    #pragma unroll
    for (int o = 1; o < 32; o <<= 1) {
        int t = __shfl_up_sync(0xffffffffu, v, o);
        if (lane >= o) v += t;
    }
    __shared__ int ws[32];
    if (lane == 31) ws[wid] = v;
    __syncthreads();
    if (wid == 0) {
        int w = ws[lane];
        #pragma unroll
        for (int o = 1; o < 32; o <<= 1) {
            int t = __shfl_up_sync(0xffffffffu, w, o);
            if (lane >= o) w += t;
        }
        ws[lane] = w;
    }
    __syncthreads();
    if (wid > 0) v += ws[wid - 1];
    if (i < n) g_scantmp[i] = v;
    if (tid == 1023) g_bsums[blockIdx.x] = v;
}
__global__ void k_scan_sums(int nb) {
    int tid = threadIdx.x, lane = tid & 31, wid = tid >> 5;
    int orig = (tid < nb) ? g_bsums[tid] : 0;
    int v = orig;
    #pragma unroll
    for (int o = 1; o < 32; o <<= 1) {
        int t = __shfl_up_sync(0xffffffffu, v, o);
        if (lane >= o) v += t;
    }
    __shared__ int ws[4];
    if (lane == 31) ws[wid] = v;
    __syncthreads();
    int add = 0;
    #pragma unroll
    for (int w = 0; w < 4; w++)
        if (w < wid) add += ws[w];
    if (tid < nb) g_bsums[tid] = v + add - orig;
}
__global__ void k_finalize(int n) {
    int i = blockIdx.x * 1024 + threadIdx.x;
    if (i >= n) return;
    int incl = g_scantmp[i] + g_bsums[blockIdx.x];
    int d = g_deg[i];
    int excl = incl - d;
    g_cursor[i] = excl;
    g_rowptr[i] = excl;
    if (i == n - 1) g_rowptr[n] = incl;
    g_dinv[i] = rsqrtf((float)(d + 1));
}
__global__ void k_scatter(const int* __restrict__ src,
                          const int* __restrict__ dst, int e) {
    int i = blockIdx.x * blockDim.x + threadIdx.x;
    if (i < e) {
        int d = dst[i];
        int p = atomicAdd(&g_cursor[d], 1);
        g_col[p] = src[i];
    }
}

// ---------------- W prep ----------------------------------------------------
__global__ void k_wconv(const float* __restrict__ W, int slot) {
    int idx = blockIdx.x * blockDim.x + threadIdx.x;
    if (idx >= 128 * 128) return;
    int n = idx >> 7, k = idx & 127;
    float w = W[(size_t)k * 128 + n];
    __nv_bfloat16 h = __float2bfloat16_rn(w);
    __nv_bfloat16 l = __float2bfloat16_rn(w - __bfloat162float(h));
    g_Wth[slot][n * 128 + k] = h;
    g_Wtl[slot][n * 128 + k] = l;
}

// ---------------- mma / ldmatrix / cp.async helpers --------------------------
__device__ __forceinline__ void mma_bf16(float* c, const uint32_t* a,
                                         const uint32_t* b) {
    asm volatile(
        "mma.sync.aligned.m16n8k16.row.col.f32.bf16.bf16.f32 "
        "{%0,%1,%2,%3}, {%4,%5,%6,%7}, {%8,%9}, {%0,%1,%2,%3};"
        : "+f"(c[0]), "+f"(c[1]), "+f"(c[2]), "+f"(c[3])
        : "r"(a[0]), "r"(a[1]), "r"(a[2]), "r"(a[3]), "r"(b[0]), "r"(b[1]));
}
__device__ __forceinline__ void ldm_x4(uint32_t& r0, uint32_t& r1,
                                       uint32_t& r2, uint32_t& r3,
                                       uint32_t addr) {
    asm volatile(
        "ldmatrix.sync.aligned.m8n8.x4.shared.b16 {%0,%1,%2,%3}, [%4];"
        : "=r"(r0), "=r"(r1), "=r"(r2), "=r"(r3) : "r"(addr));
}
__device__ __forceinline__ uint32_t smem_u32(const void* p) {
    uint32_t a;
    asm("{ .reg .u64 t; cvta.to.shared.u64 t, %1; cvt.u32.u64 %0, t; }"
        : "=r"(a) : "l"(p));
    return a;
}
__device__ __forceinline__ void cp_async16(uint32_t saddr, const void* gptr) {
    asm volatile("cp.async.ca.shared.global [%0], [%1], 16;"
                 :: "r"(saddr), "l"(gptr) : "memory");
}
#define CP_COMMIT() asm volatile("cp.async.commit_group;" ::: "memory")
#define CP_WAIT0()  asm volatile("cp.async.wait_group 0;" ::: "memory")

// ---------------- pipelined split-bf16 tensor GEMM ---------------------------
#define KP 40
#define ARRB 10240u
template <int A_SEL>
__global__ void __launch_bounds__(256, 2)
gemm128_mma_k(const float* __restrict__ Ap, int wslot, int M) {
    const float* __restrict__ A = (A_SEL == 0) ? Ap : (const float*)g_G;
    float* __restrict__ C = (float*)g_H;
    extern __shared__ char dyns[];

    const int tid = threadIdx.x;
    const int wid = tid >> 5;
    const int lane = tid & 31;
    const int gid = lane >> 2;
    const int tig = lane & 3;
    const int mw = wid & 3;
    const int nw = wid >> 2;
    const int rowBase = blockIdx.x * 128;

    const int ar  = tid >> 1;
    const int akl = (tid & 1) * 16;
    const int wn  = tid >> 1;
    const int wkl = (tid & 1) * 16;

    const int lr = lane & 7;
    const int g8 = lane >> 3;
    const int a_row = mw * 32 + (g8 & 1) * 8 + lr;
    const int a_col = (g8 >> 1) * 8;
    const int b_row = nw * 64 + (g8 >> 1) * 8 + lr;
    const int b_col = (g8 & 1) * 8;

    const uint32_t sbase = smem_u32(dyns);
    const uint32_t ashb = sbase;
    const uint32_t aslb = sbase + ARRB;

    const int gr = rowBase + ar;
    const bool valid = (gr < M);

    const __nv_bfloat16* __restrict__ Wth = g_Wth[wslot];
    const __nv_bfloat16* __restrict__ Wtl = g_Wtl[wslot];

    float acc[2][8][4];
    #pragma unroll
    for (int i = 0; i < 2; i++)
        #pragma unroll
        for (int j = 0; j < 8; j++)
            #pragma unroll
            for (int q = 0; q < 4; q++) acc[i][j][q] = 0.f;

    auto ldg_A = [&](int kt, float4* v) {
        #pragma unroll
        for (int j = 0; j < 4; j++)
            v[j] = valid
                ? *(const float4*)&A[(size_t)gr * 128 + kt + akl + j * 4]
                : make_float4(0.f, 0.f, 0.f, 0.f);
    };
    auto cvt_sts_A = [&](const float4* v) {
        uint32_t hw[8], lw[8];
        #pragma unroll
        for (int j = 0; j < 4; j++) {
            __nv_bfloat162 h0 = __float22bfloat162_rn(make_float2(v[j].x, v[j].y));
            __nv_bfloat162 h1 = __float22bfloat162_rn(make_float2(v[j].z, v[j].w));
            float2 hf0 = __bfloat1622float2(h0);
            float2 hf1 = __bfloat1622float2(h1);
            __nv_bfloat162 l0 = __float22bfloat162_rn(
                make_float2(v[j].x - hf0.x, v[j].y - hf0.y));
            __nv_bfloat162 l1 = __float22bfloat162_rn(
                make_float2(v[j].z - hf1.x, v[j].w - hf1.y));
            hw[j * 2 + 0] = *(uint32_t*)&h0;
            hw[j * 2 + 1] = *(uint32_t*)&h1;
            lw[j * 2 + 0] = *(uint32_t*)&l0;
            lw[j * 2 + 1] = *(uint32_t*)&l1;
        }
        char* a0 = dyns + (ar * KP + akl) * 2;
        *(uint4*)(a0)            = make_uint4(hw[0], hw[1], hw[2], hw[3]);
        *(uint4*)(a0 + 16)       = make_uint4(hw[4], hw[5], hw[6], hw[7]);
        *(uint4*)(a0 + ARRB)     = make_uint4(lw[0], lw[1], lw[2], lw[3]);
        *(uint4*)(a0 + ARRB + 16)= make_uint4(lw[4], lw[5], lw[6], lw[7]);
    };
    auto stage_W = [&](int kt, int buf) {
        const size_t gbase = (size_t)wn * 128 + kt + wkl;
        const uint32_t s = sbase + 20480u + (uint32_t)buf * 20480u +
                           (uint32_t)(wn * KP + wkl) * 2;
        cp_async16(s,            &Wth[gbase]);
        cp_async16(s + 16,       &Wth[gbase + 8]);
        cp_async16(s + ARRB,     &Wtl[gbase]);
        cp_async16(s + ARRB + 16,&Wtl[gbase + 8]);
    };

    // prologue
    {
        float4 av[4];
        ldg_A(0, av);
        stage_W(0, 0);
        CP_COMMIT();
        cvt_sts_A(av);
        CP_WAIT0();
    }
    __syncthreads();

    #pragma unroll
    for (int kt = 0; kt < 4; kt++) {
        const int b = kt & 1;
        float4 av[4];
        if (kt < 3) {
            ldg_A((kt + 1) * 32, av);
            stage_W((kt + 1) * 32, 1 - b);
            CP_COMMIT();
        }
        const uint32_t wshb = sbase + 20480u + (uint32_t)b * 20480u;
        const uint32_t wslb = wshb + ARRB;
        #pragma unroll
        for (int ks = 0; ks < 32; ks += 16) {
            uint32_t Ah[2][4], Al[2][4];
            #pragma unroll
            for (int mt = 0; mt < 2; mt++) {
                const uint32_t off =
                    (uint32_t)((a_row + mt * 16) * KP + ks + a_col) * 2;
                ldm_x4(Ah[mt][0], Ah[mt][1], Ah[mt][2], Ah[mt][3], ashb + off);
                ldm_x4(Al[mt][0], Al[mt][1], Al[mt][2], Al[mt][3], aslb + off);
            }
            #pragma unroll
            for (int ntp = 0; ntp < 4; ntp++) {
                uint32_t Bh[2][2], Bl[2][2];
                const uint32_t off =
                    (uint32_t)((b_row + ntp * 16) * KP + ks + b_col) * 2;
                ldm_x4(Bh[0][0], Bh[0][1], Bh[1][0], Bh[1][1], wshb + off);
                ldm_x4(Bl[0][0], Bl[0][1], Bl[1][0], Bl[1][1], wslb + off);
                #pragma unroll
                for (int mt = 0; mt < 2; mt++)
                    #pragma unroll
                    for (int j = 0; j < 2; j++)
                        mma_bf16(acc[mt][2 * ntp + j], Ah[mt], Bh[j]);
                #pragma unroll
                for (int mt = 0; mt < 2; mt++)
                    #pragma unroll
                    for (int j = 0; j < 2; j++)
                        mma_bf16(acc[mt][2 * ntp + j], Ah[mt], Bl[j]);
                #pragma unroll
                for (int mt = 0; mt < 2; mt++)
                    #pragma unroll
                    for (int j = 0; j < 2; j++)
                        mma_bf16(acc[mt][2 * ntp + j], Al[mt], Bh[j]);
            }
        }
        __syncthreads();
        if (kt < 3) {
            cvt_sts_A(av);
            CP_WAIT0();
        }
        __syncthreads();
    }

    // epilogue
    #pragma unroll
    for (int mt = 0; mt < 2; mt++) {
        const int r = rowBase + mw * 32 + mt * 16 + gid;
        #pragma unroll
        for (int nt = 0; nt < 8; nt++) {
            const int col = nw * 64 + nt * 8 + tig * 2;
            if (r < M)
                *(float2*)&C[(size_t)r * 128 + col] =
                    make_float2(acc[mt][nt][0], acc[mt][nt][1]);
            if (r + 8 < M)
                *(float2*)&C[(size_t)(r + 8) * 128 + col] =
                    make_float2(acc[mt][nt][2], acc[mt][nt][3]);
        }
    }
}

// ---------------- small GEMM for layer 3 ------------------------------------
__global__ void gemm40_k(const float* __restrict__ W, int M) {
    const float* __restrict__ A = (const float*)g_G;
    float* __restrict__ C = (float*)g_H;
    constexpr int BM = 64, BK = 32, K = 128, BN = 64, NA = 40;
    __shared__ float As[BM][BK];
    __shared__ float Ws[BK][BN];
    int tid = threadIdx.x;
    int tx = tid % 16;
    int ty = tid / 16;
    int rowBase = blockIdx.x * BM;

    float acc[4][4];
    #pragma unroll
    for (int i = 0; i < 4; i++)
        #pragma unroll
        for (int j = 0; j < 4; j++) acc[i][j] = 0.f;

    for (int kt = 0; kt < K; kt += BK) {
        #pragma unroll
        for (int t = 0; t < (BM * BK) / 256; t++) {
            int idx = tid + t * 256;
            int r = idx / BK, kk = idx % BK;
            int gr = rowBase + r;
            As[r][kk] = (gr < M) ? A[(size_t)gr * K + kt + kk] : 0.f;
        }
        #pragma unroll
        for (int t = 0; t < (BK * BN) / 256; t++) {
            int idx = tid + t * 256;
            int r = idx / BN, c = idx % BN;
            Ws[r][c] = (c < NA) ? W[(kt + r) * NA + c] : 0.f;
        }
        __syncthreads();
        #pragma unroll
        for (int kk = 0; kk < BK; kk++) {
            float b0 = Ws[kk][tx * 4 + 0];
            float b1 = Ws[kk][tx * 4 + 1];
            float b2 = Ws[kk][tx * 4 + 2];
            float b3 = Ws[kk][tx * 4 + 3];
            #pragma unroll
            for (int i = 0; i < 4; i++) {
                float a = As[ty * 4 + i][kk];
                acc[i][0] += a * b0;
                acc[i][1] += a * b1;
                acc[i][2] += a * b2;
                acc[i][3] += a * b3;
            }
        }
        __syncthreads();
    }
    #pragma unroll
    for (int i = 0; i < 4; i++) {
        int gr = rowBase + ty * 4 + i;
        if (gr >= M) continue;
        #pragma unroll
        for (int j = 0; j < 4; j++) {
            int c = tx * 4 + j;
            if (c < NA) C[(size_t)gr * NA + c] = acc[i][j];
        }
    }
}

// ---------------- aggregation, F=128 ----------------------------------------
__global__ void agg128_k(const float* __restrict__ bias, int relu, int n) {
    int node = blockIdx.x * (blockDim.x >> 5) + (threadIdx.x >> 5);
    if (node >= n) return;
    int lane = threadIdx.x & 31;
    const float4* __restrict__ H4 = (const float4*)g_H;
    float* __restrict__ O = (float*)g_G;
    float di = g_dinv[node];
    float4 h = H4[(size_t)node * 32 + lane];
    float ax = di * h.x, ay = di * h.y, az = di * h.z, aw = di * h.w;
    int p = g_rowptr[node], pend = g_rowptr[node + 1];
    for (; p + 4 <= pend; p += 4) {
        int s0 = g_col[p], s1 = g_col[p + 1], s2 = g_col[p + 2], s3 = g_col[p + 3];
        float d0 = g_dinv[s0], d1 = g_dinv[s1], d2 = g_dinv[s2], d3 = g_dinv[s3];
        float4 h0 = H4[(size_t)s0 * 32 + lane];
        float4 h1 = H4[(size_t)s1 * 32 + lane];
        float4 h2 = H4[(size_t)s2 * 32 + lane];
        float4 h3 = H4[(size_t)s3 * 32 + lane];
        ax += d0 * h0.x; ay += d0 * h0.y; az += d0 * h0.z; aw += d0 * h0.w;
        ax += d1 * h1.x; ay += d1 * h1.y; az += d1 * h1.z; aw += d1 * h1.w;
        ax += d2 * h2.x; ay += d2 * h2.y; az += d2 * h2.z; aw += d2 * h2.w;
        ax += d3 * h3.x; ay += d3 * h3.y; az += d3 * h3.z; aw += d3 * h3.w;
    }
    for (; p < pend; p++) {
        int s = g_col[p];
        float ds = g_dinv[s];
        float4 hs = H4[(size_t)s * 32 + lane];
        ax += ds * hs.x; ay += ds * hs.y; az += ds * hs.z; aw += ds * hs.w;
    }
    float4 bv = ((const float4*)bias)[lane];
    float ox = di * ax + bv.x, oy = di * ay + bv.y;
    float oz = di * az + bv.z, ow = di * aw + bv.w;
    if (relu) {
        ox = fmaxf(ox, 0.f); oy = fmaxf(oy, 0.f);
        oz = fmaxf(oz, 0.f); ow = fmaxf(ow, 0.f);
    }
    ((float4*)O)[(size_t)node * 32 + lane] = make_float4(ox, oy, oz, ow);
}

// ---------------- aggregation, F=40 ----------------------------------------
__global__ void agg40_k(const float* __restrict__ bias, float* __restrict__ O, int n) {
    int node = blockIdx.x * (blockDim.x >> 5) + (threadIdx.x >> 5);
    if (node >= n) return;
    int lane = threadIdx.x & 31;
    const float* __restrict__ H = (const float*)g_H;
    bool hi = (lane < 8);
    float di = g_dinv[node];
    float a0 = di * H[(size_t)node * 40 + lane];
    float a1 = hi ? di * H[(size_t)node * 40 + 32 + lane] : 0.f;
    int p = g_rowptr[node], pend = g_rowptr[node + 1];
    for (; p + 2 <= pend; p += 2) {
        int s0 = g_col[p], s1 = g_col[p + 1];
        float d0 = g_dinv[s0], d1 = g_dinv[s1];
        a0 += d0 * H[(size_t)s0 * 40 + lane] + d1 * H[(size_t)s1 * 40 + lane];
        if (hi) {
            a1 += d0 * H[(size_t)s0 * 40 + 32 + lane];
            a1 += d1 * H[(size_t)s1 * 40 + 32 + lane];
        }
    }
    for (; p < pend; p++) {
        int s = g_col[p];
        float ds = g_dinv[s];
        a0 += ds * H[(size_t)s * 40 + lane];
        if (hi) a1 += ds * H[(size_t)s * 40 + 32 + lane];
    }
    O[(size_t)node * 40 + lane] = di * a0 + bias[lane];
    if (hi) O[(size_t)node * 40 + 32 + lane] = di * a1 + bias[32 + lane];
}

// ---------------- launch ----------------------------------------------------
// Fork/join: CSR build runs on a side stream concurrently with the layer-1
// GEMM (independent data). Standard event-based capture fork — graph-legal.
extern "C" void kernel_launch(void* const* d_in, const int* in_sizes, int n_in,
                              void* d_out, int out_size) {
    const float* x   = (const float*)d_in[0];
    const int*   ei  = (const int*)d_in[1];
    const float* W1  = (const float*)d_in[2];
    const float* b1  = (const float*)d_in[3];
    const float* Wm  = (const float*)d_in[4];
    const float* bm  = (const float*)d_in[5];
    const float* W2  = (const float*)d_in[6];
    const float* b2  = (const float*)d_in[7];
    float* out = (float*)d_out;

    const int n = NN, e = NE;
    const int* src = ei;
    const int* dst = ei + e;

    const int scanBlocks = (n + 1023) / 1024;
    const int tcBlocks  = (n + 127) / 128;
    const int aggBlocks = (n + 7) / 8;
    const int DSMEM = 61440;

    cudaFuncSetAttribute(gemm128_mma_k<0>,
                         cudaFuncAttributeMaxDynamicSharedMemorySize, DSMEM);
    cudaFuncSetAttribute(gemm128_mma_k<1>,
                         cudaFuncAttributeMaxDynamicSharedMemorySize, DSMEM);

    cudaStream_t s2;
    cudaStreamCreateWithFlags(&s2, cudaStreamNonBlocking);
    cudaEvent_t e1, e2;
    cudaEventCreateWithFlags(&e1, cudaEventDisableTiming);
    cudaEventCreateWithFlags(&e2, cudaEventDisableTiming);

    // fork side stream from the capture origin
    cudaEventRecord(e1, 0);
    cudaStreamWaitEvent(s2, e1, 0);

    // side stream: CSR build (independent of GEMM-1)
    k_zero_deg<<<(n + 255) / 256, 256, 0, s2>>>(n);
    k_count<<<(e + 255) / 256, 256, 0, s2>>>(dst, e);
    k_scan_block<<<scanBlocks, 1024, 0, s2>>>(n);
    k_scan_sums<<<1, 128, 0, s2>>>(scanBlocks);
    k_finalize<<<scanBlocks, 1024, 0, s2>>>(n);
    k_scatter<<<(e + 255) / 256, 256, 0, s2>>>(src, dst, e);
    cudaEventRecord(e2, s2);

    // main stream: weight conversion + layer-1 GEMM (overlaps CSR build)
    k_wconv<<<64, 256>>>(W1, 0);
    k_wconv<<<64, 256>>>(Wm, 1);
    gemm128_mma_k<0><<<tcBlocks, 256, DSMEM>>>(x, 0, n);

    // join: agg needs CSR + GEMM-1
    cudaStreamWaitEvent(0, e2, 0);
    agg128_k<<<aggBlocks, 256>>>(b1, 1, n);

    // layer 2
    gemm128_mma_k<1><<<tcBlocks, 256, DSMEM>>>(nullptr, 1, n);
    agg128_k<<<aggBlocks, 256>>>(bm, 1, n);

    // layer 3
    gemm40_k<<<(n + 63) / 64, 256>>>(W2, n);
    agg40_k<<<aggBlocks, 256>>>(b2, out, n);
}